// round 14
// baseline (speedup 1.0000x reference)
#include <cuda_runtime.h>
#include <cuda_fp16.h>
#include <math.h>
#include <stdint.h>

#define BATCH 2
#define SEQ   4096
#define DIM   1024

#define NQ  ((size_t)BATCH * SEQ * DIM)
#define NP  ((size_t)BATCH * SEQ * SEQ)
#define NW  ((size_t)DIM * DIM)

// ---- device scratch ----
__device__ __half g_xh[NQ],  g_xl[NQ];
__device__ __half g_W3h[3 * NW], g_W3l[3 * NW];   // Wq|Wk|Wv stacked (hi/lo)
__device__ __half g_Woh[NW], g_Wol[NW];
__device__ __half g_QKVh[3 * NQ], g_QKVl[3 * NQ]; // Q|K split; slot 2 holds Wvo (hi)
__device__ __half g_O[NQ];                         // U = x @ Wvo, fp16
__device__ __half g_P[NP];                         // un-normalized probs exp(s-18), fp16
__device__ float  g_R[(size_t)BATCH * SEQ];        // row sums of exp(s-18)
__device__ float  g_BC[DIM];                       // bcomb = bv@Wo + bo

// ---------------------------------------------------------------------------
// PTX helpers
// ---------------------------------------------------------------------------
__device__ __forceinline__ uint32_t cvta_s(const void* p) {
    return (uint32_t)__cvta_generic_to_shared(p);
}
__device__ __forceinline__ void cp16(uint32_t dst, const void* src) {
    asm volatile("cp.async.cg.shared.global [%0], [%1], 16;" :: "r"(dst), "l"(src));
}
__device__ __forceinline__ void ldmx4(uint32_t* r, uint32_t a) {
    asm volatile("ldmatrix.sync.aligned.m8n8.x4.shared.b16 {%0,%1,%2,%3}, [%4];"
                 : "=r"(r[0]), "=r"(r[1]), "=r"(r[2]), "=r"(r[3]) : "r"(a));
}
__device__ __forceinline__ void ldmx4t(uint32_t* r, uint32_t a) {
    asm volatile("ldmatrix.sync.aligned.m8n8.x4.trans.shared.b16 {%0,%1,%2,%3}, [%4];"
                 : "=r"(r[0]), "=r"(r[1]), "=r"(r[2]), "=r"(r[3]) : "r"(a));
}
__device__ __forceinline__ void mma16816(float* c, const uint32_t* a, const uint32_t* b) {
    asm volatile(
        "mma.sync.aligned.m16n8k16.row.col.f32.f16.f16.f32 "
        "{%0,%1,%2,%3}, {%4,%5,%6,%7}, {%8,%9}, {%0,%1,%2,%3};"
        : "+f"(c[0]), "+f"(c[1]), "+f"(c[2]), "+f"(c[3])
        : "r"(a[0]), "r"(a[1]), "r"(a[2]), "r"(a[3]), "r"(b[0]), "r"(b[1]));
}
__device__ __forceinline__ __half2 hi2(float a, float b) {
    return __floats2half2_rn(a, b);
}
__device__ __forceinline__ __half2 lo2(float a, float b, __half2 h) {
    return __floats2half2_rn(a - __half2float(__low2half(h)),
                             b - __half2float(__high2half(h)));
}

// ---------------------------------------------------------------------------
// Split-fp16 GEMM (R7/R9 structure, mainloop UNchanged): CTA 128x128, BK=32,
// 256 thr, warps 2x4, warp tile 64x32, 2-stage cp.async.
//   passes: Ah*Bh [+ Ah*Bl if SPLIT_B] [+ Al*Bh if SPLIT_A]
//   OUT: 1 = split fp16 hi/lo(+bias), 2 = single fp16(+bias),
//        3 = exp epilogue: P=fp16(exp(alpha*acc-18)) + atomic row sums,
//        5 = fp32, scaled by 1/rsum[z*SEQ+row], +bias.
// ---------------------------------------------------------------------------
constexpr int LDA    = 40;   // 32 + 8 pad
constexpr int LDB_NN = 136;  // 128 + 8 pad
constexpr float EXPC = 18.0f;

template <bool TRANSB, bool SPLIT_A, bool SPLIT_B>
__device__ __forceinline__ void load_stage14(
    __half* sb,
    const __half* Ah, const __half* Al,
    const __half* Bh, const __half* Bl,
    int k0, int K, int N, int tid)
{
    constexpr int AE = 128 * LDA;                        // 5120
    constexpr int AT = SPLIT_A ? 2 * AE : AE;
    constexpr int BE = TRANSB ? 128 * LDA : 32 * LDB_NN; // 5120 / 4352
    __half* sAh = sb;
    __half* sAl = sb + AE;
    __half* sBh = sb + AT;
    __half* sBl = sb + AT + BE;

#pragma unroll
    for (int i = 0; i < 2; i++) {
        int c = tid + (i << 8);
        int row = c >> 2, col = (c & 3) << 3;
        size_t g = (size_t)row * K + k0 + col;
        uint32_t so = row * LDA + col;
        cp16(cvta_s(sAh + so), Ah + g);
        if (SPLIT_A) cp16(cvta_s(sAl + so), Al + g);
    }
    if (TRANSB) {
#pragma unroll
        for (int i = 0; i < 2; i++) {
            int c = tid + (i << 8);
            int row = c >> 2, col = (c & 3) << 3;
            size_t g = (size_t)row * K + k0 + col;
            uint32_t so = row * LDA + col;
            cp16(cvta_s(sBh + so), Bh + g);
            if (SPLIT_B) cp16(cvta_s(sBl + so), Bl + g);
        }
    } else {
#pragma unroll
        for (int i = 0; i < 2; i++) {
            int c = tid + (i << 8);
            int row = c >> 4, col = (c & 15) << 3;
            size_t g = (size_t)(k0 + row) * N + col;
            uint32_t so = row * LDB_NN + col;
            cp16(cvta_s(sBh + so), Bh + g);
            if (SPLIT_B) cp16(cvta_s(sBl + so), Bl + g);
        }
    }
    asm volatile("cp.async.commit_group;");
}

template <bool TRANSB, bool SPLIT_A, bool SPLIT_B, int OUT>
__global__ __launch_bounds__(256, 2)
void gemm14(const __half* __restrict__ Agh, const __half* __restrict__ Agl,
            const __half* __restrict__ Bgh, const __half* __restrict__ Bgl,
            float* __restrict__ Cf,
            __half* __restrict__ Ch, __half* __restrict__ Cl,
            const float* __restrict__ b0, const float* __restrict__ b1,
            const float* __restrict__ b2,
            float* __restrict__ rsum,
            int N, int K, float alpha,
            size_t sA, size_t sB, size_t sC)
{
    extern __shared__ __align__(16) char smraw[];
    __half* sm = (__half*)smraw;
    constexpr int AE    = 128 * LDA;
    constexpr int AT    = SPLIT_A ? 2 * AE : AE;
    constexpr int BE    = TRANSB ? 128 * LDA : 32 * LDB_NN;
    constexpr int BT    = SPLIT_B ? 2 * BE : BE;
    constexpr int STAGE = AT + BT;
    constexpr int LDB   = TRANSB ? LDA : LDB_NN;

    const int tid  = threadIdx.x;
    const int lane = tid & 31;
    const int warp = tid >> 5;
    const int wm   = warp & 1;    // 2 row groups of 64
    const int wn   = warp >> 1;   // 4 col groups of 32
    const int z    = blockIdx.z;
    const int bm = blockIdx.y << 7, bn = blockIdx.x << 7;

    const float* bias = (z == 0) ? b0 : (z == 1) ? b1 : b2;

    const __half* Abh = Agh + z * sA + (size_t)bm * K;
    const __half* Abl = SPLIT_A ? (Agl + z * sA + (size_t)bm * K) : nullptr;
    const __half *Bbh, *Bbl;
    if (TRANSB) {
        Bbh = Bgh + z * sB + (size_t)bn * K;
        Bbl = SPLIT_B ? (Bgl + z * sB + (size_t)bn * K) : nullptr;
    } else {
        Bbh = Bgh + z * sB + bn;
        Bbl = SPLIT_B ? (Bgl + z * sB + bn) : nullptr;
    }

    float acc[4][4][4];
#pragma unroll
    for (int i = 0; i < 4; i++)
#pragma unroll
        for (int j = 0; j < 4; j++)
#pragma unroll
            for (int l = 0; l < 4; l++) acc[i][j][l] = 0.f;

    const int lm_r = lane & 15;
    const int lm_c = (lane >> 4) << 3;
    const int tr_k = (lane & 7) | (((lane >> 3) & 1) << 3);
    const int tr_n = (lane >> 4) << 3;

    load_stage14<TRANSB, SPLIT_A, SPLIT_B>(sm, Abh, Abl, Bbh, Bbl, 0, K, N, tid);

    const int nT = K >> 5;
    for (int kt = 0; kt < nT; kt++) {
        asm volatile("cp.async.wait_group 0;");
        __syncthreads();
        if (kt + 1 < nT)
            load_stage14<TRANSB, SPLIT_A, SPLIT_B>(sm + ((kt + 1) & 1) * STAGE,
                                                   Abh, Abl, Bbh, Bbl,
                                                   (kt + 1) << 5, K, N, tid);

        __half* cs  = sm + (kt & 1) * STAGE;
        __half* sAh = cs;
        __half* sAl = cs + AE;
        __half* sBh = cs + AT;
        __half* sBl = cs + AT + BE;

#pragma unroll
        for (int ks = 0; ks < 2; ks++) {
            uint32_t af[4][4], bh[4][2], bl[4][2];

            if (TRANSB) {
#pragma unroll
                for (int h = 0; h < 2; h++) {
                    int row = wn * 32 + h * 16 + lm_r;
                    int col = ks * 16 + lm_c;
                    uint32_t t[4];
                    ldmx4(t, cvta_s(&sBh[row * LDB + col]));
                    bh[2 * h][0] = t[0]; bh[2 * h][1] = t[2];
                    bh[2 * h + 1][0] = t[1]; bh[2 * h + 1][1] = t[3];
                    if (SPLIT_B) {
                        ldmx4(t, cvta_s(&sBl[row * LDB + col]));
                        bl[2 * h][0] = t[0]; bl[2 * h][1] = t[2];
                        bl[2 * h + 1][0] = t[1]; bl[2 * h + 1][1] = t[3];
                    }
                }
            } else {
                int krow = ks * 16 + tr_k;
#pragma unroll
                for (int h = 0; h < 2; h++) {
                    int col = wn * 32 + h * 16 + tr_n;
                    uint32_t t[4];
                    ldmx4t(t, cvta_s(&sBh[krow * LDB + col]));
                    bh[2 * h][0] = t[0]; bh[2 * h][1] = t[1];
                    bh[2 * h + 1][0] = t[2]; bh[2 * h + 1][1] = t[3];
                    if (SPLIT_B) {
                        ldmx4t(t, cvta_s(&sBl[krow * LDB + col]));
                        bl[2 * h][0] = t[0]; bl[2 * h][1] = t[1];
                        bl[2 * h + 1][0] = t[2]; bl[2 * h + 1][1] = t[3];
                    }
                }
            }

            // pass 1 (+2): Ah*Bh (+ Ah*Bl)
#pragma unroll
            for (int mf = 0; mf < 4; mf++) {
                int row = wm * 64 + mf * 16 + lm_r;
                ldmx4(af[mf], cvta_s(&sAh[row * LDA + ks * 16 + lm_c]));
            }
#pragma unroll
            for (int mf = 0; mf < 4; mf++)
#pragma unroll
                for (int nf = 0; nf < 4; nf++) {
                    mma16816(acc[mf][nf], af[mf], bh[nf]);
                    if (SPLIT_B) mma16816(acc[mf][nf], af[mf], bl[nf]);
                }
            if (SPLIT_A) {
                // pass 3: Al*Bh
#pragma unroll
                for (int mf = 0; mf < 4; mf++) {
                    int row = wm * 64 + mf * 16 + lm_r;
                    ldmx4(af[mf], cvta_s(&sAl[row * LDA + ks * 16 + lm_c]));
                }
#pragma unroll
                for (int mf = 0; mf < 4; mf++)
#pragma unroll
                    for (int nf = 0; nf < 4; nf++)
                        mma16816(acc[mf][nf], af[mf], bh[nf]);
            }
        }
    }

    // ---- epilogue
    const int g  = lane >> 2;
    const int t2 = (lane & 3) << 1;

    if (OUT == 3) {
        // exp + un-normalized P (fp16) + atomic row sums
        __half* Chb = Ch + z * sC + (size_t)bm * N + bn;
        float rs[4][2];
#pragma unroll
        for (int mf = 0; mf < 4; mf++) { rs[mf][0] = 0.f; rs[mf][1] = 0.f; }
#pragma unroll
        for (int mf = 0; mf < 4; mf++) {
            int r0 = wm * 64 + mf * 16 + g;
#pragma unroll
            for (int nf = 0; nf < 4; nf++) {
                int c = wn * 32 + nf * 8 + t2;
                float e00 = fminf(__expf(acc[mf][nf][0] * alpha - EXPC), 60000.f);
                float e01 = fminf(__expf(acc[mf][nf][1] * alpha - EXPC), 60000.f);
                float e10 = fminf(__expf(acc[mf][nf][2] * alpha - EXPC), 60000.f);
                float e11 = fminf(__expf(acc[mf][nf][3] * alpha - EXPC), 60000.f);
                *(__half2*)(Chb + (size_t)r0 * N + c)       = hi2(e00, e01);
                *(__half2*)(Chb + (size_t)(r0 + 8) * N + c) = hi2(e10, e11);
                rs[mf][0] += e00 + e01;
                rs[mf][1] += e10 + e11;
            }
        }
#pragma unroll
        for (int mf = 0; mf < 4; mf++)
#pragma unroll
            for (int s = 0; s < 2; s++) {
                float v = rs[mf][s];
                v += __shfl_xor_sync(0xffffffffu, v, 1);
                v += __shfl_xor_sync(0xffffffffu, v, 2);
                rs[mf][s] = v;
            }
        float* rows = (float*)smraw;   // reuse stage smem (mainloop done)
        __syncthreads();
        if (tid < 128) rows[tid] = 0.f;
        __syncthreads();
        if ((lane & 3) == 0) {
#pragma unroll
            for (int mf = 0; mf < 4; mf++) {
                atomicAdd(&rows[wm * 64 + mf * 16 + g],     rs[mf][0]);
                atomicAdd(&rows[wm * 64 + mf * 16 + g + 8], rs[mf][1]);
            }
        }
        __syncthreads();
        if (tid < 128)
            atomicAdd(&rsum[(size_t)z * SEQ + bm + tid], rows[tid]);
        return;
    }

#pragma unroll
    for (int mf = 0; mf < 4; mf++) {
        int r0 = wm * 64 + mf * 16 + g;
        float sc0 = alpha, sc1 = alpha;
        if (OUT == 5) {
            sc0 = 1.f / rsum[(size_t)z * SEQ + bm + r0];
            sc1 = 1.f / rsum[(size_t)z * SEQ + bm + r0 + 8];
        }
#pragma unroll
        for (int nf = 0; nf < 4; nf++) {
            int c = wn * 32 + nf * 8 + t2;
            float bb0 = 0.f, bb1 = 0.f;
            if (bias) { bb0 = bias[bn + c]; bb1 = bias[bn + c + 1]; }
            float v00 = acc[mf][nf][0] * sc0 + bb0;
            float v01 = acc[mf][nf][1] * sc0 + bb1;
            float v10 = acc[mf][nf][2] * sc1 + bb0;
            float v11 = acc[mf][nf][3] * sc1 + bb1;
            if (OUT == 1) {
                __half* Chb = Ch + z * sC + (size_t)bm * N + bn;
                __half* Clb = Cl + z * sC + (size_t)bm * N + bn;
                __half2 h0 = hi2(v00, v01), h1 = hi2(v10, v11);
                __half2 L0 = lo2(v00, v01, h0), L1 = lo2(v10, v11, h1);
                *(__half2*)(Chb + (size_t)r0 * N + c)       = h0;
                *(__half2*)(Chb + (size_t)(r0 + 8) * N + c) = h1;
                *(__half2*)(Clb + (size_t)r0 * N + c)       = L0;
                *(__half2*)(Clb + (size_t)(r0 + 8) * N + c) = L1;
            } else if (OUT == 2) {
                __half* Chb = Ch + z * sC + (size_t)bm * N + bn;
                *(__half2*)(Chb + (size_t)r0 * N + c)       = hi2(v00, v01);
                *(__half2*)(Chb + (size_t)(r0 + 8) * N + c) = hi2(v10, v11);
            } else {
                float* Cfb = Cf + z * sC + (size_t)bm * N + bn;
                *(float2*)(Cfb + (size_t)r0 * N + c)       = make_float2(v00, v01);
                *(float2*)(Cfb + (size_t)(r0 + 8) * N + c) = make_float2(v10, v11);
            }
        }
    }
}

// ---------------------------------------------------------------------------
// merged elementwise split: x, Wq, Wk, Wv, Wo -> fp16 hi/lo; also zeros R.
// Regions (float4 units): x=NX4, then 4 weights of NW4 each.
// ---------------------------------------------------------------------------
constexpr int NX4 = (int)(NQ / 4);   // 2097152
constexpr int NW4 = (int)(NW / 4);   // 262144

__global__ __launch_bounds__(256)
void split_all(const float* __restrict__ x,
               const float* __restrict__ Wq, const float* __restrict__ Wk,
               const float* __restrict__ Wv, const float* __restrict__ Wo,
               __half* __restrict__ xh, __half* __restrict__ xl,
               __half* __restrict__ W3h, __half* __restrict__ W3l,
               __half* __restrict__ Woh, __half* __restrict__ Wol,
               float* __restrict__ R)
{
    int i = blockIdx.x * blockDim.x + threadIdx.x;
    // zero R (8192 floats = 2048 float4)
    if (i < 2048) ((float4*)R)[i] = make_float4(0.f, 0.f, 0.f, 0.f);

    const float* src;
    __half *dh, *dl;
    int o;
    if (i < NX4) {
        src = x; dh = xh; dl = xl; o = i;
    } else {
        int j = i - NX4;
        int r = j >> 18;            // / NW4
        o = j & (NW4 - 1);
        if      (r == 0) { src = Wq; dh = W3h;          dl = W3l; }
        else if (r == 1) { src = Wk; dh = W3h + NW;     dl = W3l + NW; }
        else if (r == 2) { src = Wv; dh = W3h + 2 * NW; dl = W3l + 2 * NW; }
        else             { src = Wo; dh = Woh;          dl = Wol; }
    }
    float4 v = ((const float4*)src)[o];
    __half2 h0 = hi2(v.x, v.y), h1 = hi2(v.z, v.w);
    __half2 l0 = lo2(v.x, v.y, h0), l1 = lo2(v.z, v.w, h1);
    ((__half2*)dh)[2 * o]     = h0;
    ((__half2*)dh)[2 * o + 1] = h1;
    ((__half2*)dl)[2 * o]     = l0;
    ((__half2*)dl)[2 * o + 1] = l1;
}

// bcomb[j] = sum_d bv[d] * Wo[d][j] + bo[j]   (fp32, exact path)
__global__ __launch_bounds__(256)
void bcomb_k(const float* __restrict__ bv, const float* __restrict__ Wo,
             const float* __restrict__ bo, float* __restrict__ bc)
{
    int j = blockIdx.x * 256 + threadIdx.x;
    float s = bo[j];
    for (int d = 0; d < DIM; d++)
        s += bv[d] * Wo[(size_t)d * DIM + j];
    bc[j] = s;
}

// ---------------------------------------------------------------------------
// kernel_launch
// ---------------------------------------------------------------------------
extern "C" void kernel_launch(void* const* d_in, const int* in_sizes, int n_in,
                              void* d_out, int out_size)
{
    const float* x  = (const float*)d_in[0];
    const float* Wq = (const float*)d_in[1];
    const float* bq = (const float*)d_in[2];
    const float* Wk = (const float*)d_in[3];
    const float* bk = (const float*)d_in[4];
    const float* Wv = (const float*)d_in[5];
    const float* bv = (const float*)d_in[6];
    const float* Wo = (const float*)d_in[7];
    const float* bo = (const float*)d_in[8];
    float* out = (float*)d_out;

    __half *xh, *xl, *W3h, *W3l, *Woh, *Wol, *QKVh, *QKVl, *U, *P;
    float *R, *BC;
    cudaGetSymbolAddress((void**)&xh, g_xh);     cudaGetSymbolAddress((void**)&xl, g_xl);
    cudaGetSymbolAddress((void**)&W3h, g_W3h);   cudaGetSymbolAddress((void**)&W3l, g_W3l);
    cudaGetSymbolAddress((void**)&Woh, g_Woh);   cudaGetSymbolAddress((void**)&Wol, g_Wol);
    cudaGetSymbolAddress((void**)&QKVh, g_QKVh); cudaGetSymbolAddress((void**)&QKVl, g_QKVl);
    cudaGetSymbolAddress((void**)&U, g_O);       cudaGetSymbolAddress((void**)&P, g_P);
    cudaGetSymbolAddress((void**)&R, g_R);       cudaGetSymbolAddress((void**)&BC, g_BC);

    __half* Wvoh = QKVh + 2 * NQ;   // reuse old V slot for Wvo (hi)

    // dynamic smem bytes (2 stages)
    const int SM_PROJ = 2 * 2 * (2 * 128 * LDA + 2 * 32 * LDB_NN);  // 75776
    const int SM_SC2  = 2 * 2 * (128 * LDA + 2 * 128 * LDA);        // 61440
    const int SM_1P   = 2 * 2 * (128 * LDA + 32 * LDB_NN);          // 37888
    cudaFuncSetAttribute(gemm14<false, true,  true,  1>, cudaFuncAttributeMaxDynamicSharedMemorySize, SM_PROJ);
    cudaFuncSetAttribute(gemm14<false, true,  true,  2>, cudaFuncAttributeMaxDynamicSharedMemorySize, SM_PROJ);
    cudaFuncSetAttribute(gemm14<true,  false, true,  3>, cudaFuncAttributeMaxDynamicSharedMemorySize, SM_SC2);
    cudaFuncSetAttribute(gemm14<false, false, false, 2>, cudaFuncAttributeMaxDynamicSharedMemorySize, SM_1P);
    cudaFuncSetAttribute(gemm14<false, false, false, 5>, cudaFuncAttributeMaxDynamicSharedMemorySize, SM_1P);

    const int M = BATCH * SEQ;          // 8192
    const float scale = 0.125f;         // 1/sqrt(64)
    dim3 b256(256);
    const size_t sQ = (size_t)SEQ * DIM;

    // merged pre-split (x, Wq, Wk, Wv, Wo -> hi/lo) + zero R
    split_all<<<(NX4 + 4 * NW4) / 256, b256>>>(x, Wq, Wk, Wv, Wo,
                                               xh, xl, W3h, W3l, Woh, Wol, R);

    // bcomb = bv @ Wo + bo
    bcomb_k<<<DIM / 256, b256>>>(bv, Wo, bo, BC);

    // Wvo = Wv @ Wo (3-pass, fp16 hi out)
    dim3 gWvo(DIM / 128, DIM / 128, 1);
    gemm14<false, true, true, 2><<<gWvo, b256, SM_PROJ>>>(
        W3h + 2 * NW, W3l + 2 * NW, Woh, Wol, nullptr, Wvoh, nullptr,
        nullptr, nullptr, nullptr, nullptr,
        DIM, DIM, 1.f, 0, 0, 0);

    // QK projection (3-pass, split fp16 out), z in {0,1}
    dim3 gQK(DIM / 128, M / 128, 2);
    gemm14<false, true, true, 1><<<gQK, b256, SM_PROJ>>>(
        xh, xl, W3h, W3l, nullptr, QKVh, QKVl, bq, bk, nullptr, nullptr,
        DIM, DIM, 1.f, 0, NW, NQ);

    // U = x @ Wvo (1-pass, single fp16 out, no bias)
    dim3 gU(DIM / 128, M / 128, 1);
    gemm14<false, false, false, 2><<<gU, b256, SM_1P>>>(
        xh, nullptr, Wvoh, nullptr, nullptr, U, nullptr,
        nullptr, nullptr, nullptr, nullptr,
        DIM, DIM, 1.f, 0, 0, 0);

    __half *Qh = QKVh;
    __half *Kh = QKVh + NQ, *Kl = QKVl + NQ;

    // scores + fused exp (2-pass: Qh*Kh + Qh*Kl): P = fp16(exp(scale*QK^T-18)), R += row sums
    dim3 gScore(SEQ / 128, SEQ / 128, BATCH);
    gemm14<true, false, true, 3><<<gScore, b256, SM_SC2>>>(
        Qh, nullptr, Kh, Kl, nullptr, P, nullptr, nullptr, nullptr, nullptr, R,
        SEQ, DIM, scale, sQ, sQ, (size_t)SEQ * SEQ);

    // out = (P @ U) / R[row] + bcomb (1-pass, fp32 out), z = batch
    // NOTE: sB = sQ (batch stride of U) — R13's bug was sB = 0 here.
    dim3 gPV(DIM / 128, SEQ / 128, BATCH);
    gemm14<false, false, false, 5><<<gPV, b256, SM_1P>>>(
        P, nullptr, U, nullptr, out, nullptr, nullptr,
        BC, BC, nullptr, R,
        DIM, SEQ, 1.f, (size_t)SEQ * SEQ, sQ, sQ);
}

// round 15
// speedup vs baseline: 1.0496x; 1.0496x over previous
#include <cuda_runtime.h>
#include <cuda_fp16.h>
#include <math.h>
#include <stdint.h>

#define BATCH 2
#define SEQ   4096
#define DIM   1024

#define NQ  ((size_t)BATCH * SEQ * DIM)
#define NP  ((size_t)BATCH * SEQ * SEQ)
#define NW  ((size_t)DIM * DIM)

// ---- device scratch ----
__device__ __half g_xh[NQ],  g_xl[NQ];
__device__ __half g_W3h[3 * NW], g_W3l[3 * NW];   // Wq|Wk|Wv stacked (hi/lo)
__device__ __half g_Woh[NW], g_Wol[NW];
__device__ __half g_QKVh[3 * NQ], g_QKVl[3 * NQ]; // Q|K split; slot 2: Wvo hi / scratch lo
__device__ __half g_O[NQ];                         // U = x @ Wvo, fp16
__device__ __half g_P[NP];                         // un-normalized probs exp(s-18), fp16
__device__ float  g_R[(size_t)BATCH * SEQ];        // row sums of exp(s-18)
__device__ float  g_BC[DIM];                       // bcomb = bv@Wo + bo

// ---------------------------------------------------------------------------
// PTX helpers
// ---------------------------------------------------------------------------
__device__ __forceinline__ uint32_t cvta_s(const void* p) {
    return (uint32_t)__cvta_generic_to_shared(p);
}
__device__ __forceinline__ void cp16(uint32_t dst, const void* src) {
    asm volatile("cp.async.cg.shared.global [%0], [%1], 16;" :: "r"(dst), "l"(src));
}
__device__ __forceinline__ void ldmx4(uint32_t* r, uint32_t a) {
    asm volatile("ldmatrix.sync.aligned.m8n8.x4.shared.b16 {%0,%1,%2,%3}, [%4];"
                 : "=r"(r[0]), "=r"(r[1]), "=r"(r[2]), "=r"(r[3]) : "r"(a));
}
__device__ __forceinline__ void ldmx4t(uint32_t* r, uint32_t a) {
    asm volatile("ldmatrix.sync.aligned.m8n8.x4.trans.shared.b16 {%0,%1,%2,%3}, [%4];"
                 : "=r"(r[0]), "=r"(r[1]), "=r"(r[2]), "=r"(r[3]) : "r"(a));
}
__device__ __forceinline__ void mma16816(float* c, const uint32_t* a, const uint32_t* b) {
    asm volatile(
        "mma.sync.aligned.m16n8k16.row.col.f32.f16.f16.f32 "
        "{%0,%1,%2,%3}, {%4,%5,%6,%7}, {%8,%9}, {%0,%1,%2,%3};"
        : "+f"(c[0]), "+f"(c[1]), "+f"(c[2]), "+f"(c[3])
        : "r"(a[0]), "r"(a[1]), "r"(a[2]), "r"(a[3]), "r"(b[0]), "r"(b[1]));
}
__device__ __forceinline__ __half2 hi2(float a, float b) {
    return __floats2half2_rn(a, b);
}
__device__ __forceinline__ __half2 lo2(float a, float b, __half2 h) {
    return __floats2half2_rn(a - __half2float(__low2half(h)),
                             b - __half2float(__high2half(h)));
}

// ---------------------------------------------------------------------------
// Split-fp16 GEMM (R7/R9 structure, mainloop UNchanged): CTA 128x128, BK=32,
// 256 thr, warps 2x4, warp tile 64x32, 2-stage cp.async.
//   passes: Ah*Bh [+ Ah*Bl if SPLIT_B] [+ Al*Bh if SPLIT_A]
//   OUT: 1 = split fp16 hi/lo(+bias), 2 = single fp16(+bias),
//        3 = exp epilogue: P=fp16(exp(alpha*acc-18)) + atomic row sums,
//        5 = fp32, scaled by 1/rsum[z*SEQ+row], +bias.
//   OUT==1 with z==2: alternate operands (A2,B2 -> C2), 8 valid y-blocks.
// ---------------------------------------------------------------------------
constexpr int LDA    = 40;   // 32 + 8 pad
constexpr int LDB_NN = 136;  // 128 + 8 pad
constexpr float EXPC = 18.0f;

template <bool TRANSB, bool SPLIT_A, bool SPLIT_B>
__device__ __forceinline__ void load_stage15(
    __half* sb,
    const __half* Ah, const __half* Al,
    const __half* Bh, const __half* Bl,
    int k0, int K, int N, int tid)
{
    constexpr int AE = 128 * LDA;                        // 5120
    constexpr int AT = SPLIT_A ? 2 * AE : AE;
    constexpr int BE = TRANSB ? 128 * LDA : 32 * LDB_NN; // 5120 / 4352
    __half* sAh = sb;
    __half* sAl = sb + AE;
    __half* sBh = sb + AT;
    __half* sBl = sb + AT + BE;

#pragma unroll
    for (int i = 0; i < 2; i++) {
        int c = tid + (i << 8);
        int row = c >> 2, col = (c & 3) << 3;
        size_t g = (size_t)row * K + k0 + col;
        uint32_t so = row * LDA + col;
        cp16(cvta_s(sAh + so), Ah + g);
        if (SPLIT_A) cp16(cvta_s(sAl + so), Al + g);
    }
    if (TRANSB) {
#pragma unroll
        for (int i = 0; i < 2; i++) {
            int c = tid + (i << 8);
            int row = c >> 2, col = (c & 3) << 3;
            size_t g = (size_t)row * K + k0 + col;
            uint32_t so = row * LDA + col;
            cp16(cvta_s(sBh + so), Bh + g);
            if (SPLIT_B) cp16(cvta_s(sBl + so), Bl + g);
        }
    } else {
#pragma unroll
        for (int i = 0; i < 2; i++) {
            int c = tid + (i << 8);
            int row = c >> 4, col = (c & 15) << 3;
            size_t g = (size_t)(k0 + row) * N + col;
            uint32_t so = row * LDB_NN + col;
            cp16(cvta_s(sBh + so), Bh + g);
            if (SPLIT_B) cp16(cvta_s(sBl + so), Bl + g);
        }
    }
    asm volatile("cp.async.commit_group;");
}

template <bool TRANSB, bool SPLIT_A, bool SPLIT_B, int OUT>
__global__ __launch_bounds__(256, 2)
void gemm15(const __half* __restrict__ Agh, const __half* __restrict__ Agl,
            const __half* __restrict__ Bgh, const __half* __restrict__ Bgl,
            float* __restrict__ Cf,
            __half* __restrict__ Ch, __half* __restrict__ Cl,
            const float* __restrict__ b0, const float* __restrict__ b1,
            const float* __restrict__ b2,
            float* __restrict__ rsum,
            const __half* __restrict__ A2h, const __half* __restrict__ A2l,
            const __half* __restrict__ B2h, const __half* __restrict__ B2l,
            __half* __restrict__ C2h, __half* __restrict__ C2l,
            int N, int K, float alpha,
            size_t sA, size_t sB, size_t sC)
{
    extern __shared__ __align__(16) char smraw[];
    __half* sm = (__half*)smraw;
    constexpr int AE    = 128 * LDA;
    constexpr int AT    = SPLIT_A ? 2 * AE : AE;
    constexpr int BE    = TRANSB ? 128 * LDA : 32 * LDB_NN;
    constexpr int BT    = SPLIT_B ? 2 * BE : BE;
    constexpr int STAGE = AT + BT;
    constexpr int LDB   = TRANSB ? LDA : LDB_NN;

    const int tid  = threadIdx.x;
    const int lane = tid & 31;
    const int warp = tid >> 5;
    const int wm   = warp & 1;    // 2 row groups of 64
    const int wn   = warp >> 1;   // 4 col groups of 32
    const int z    = blockIdx.z;
    const int bm = blockIdx.y << 7, bn = blockIdx.x << 7;

    const float* bias = (z == 0) ? b0 : (z == 1) ? b1 : b2;

    const __half *Abh, *Abl = nullptr, *Bbh, *Bbl = nullptr;
    __half *Cho = nullptr, *Clo = nullptr;   // OUT==1 destinations

    if (OUT == 1 && z == 2) {
        // Wvo slice: A = Wv (hi/lo) [1024,K], B = Wo (hi/lo) [K,N] NN
        if (blockIdx.y >= 8) return;
        Abh = A2h + (size_t)bm * K;
        Abl = A2l + (size_t)bm * K;
        Bbh = B2h + bn;
        Bbl = B2l + bn;
        Cho = C2h;
        Clo = C2l;
    } else {
        Abh = Agh + z * sA + (size_t)bm * K;
        if (SPLIT_A) Abl = Agl + z * sA + (size_t)bm * K;
        if (TRANSB) {
            Bbh = Bgh + z * sB + (size_t)bn * K;
            if (SPLIT_B) Bbl = Bgl + z * sB + (size_t)bn * K;
        } else {
            Bbh = Bgh + z * sB + bn;
            if (SPLIT_B) Bbl = Bgl + z * sB + bn;
        }
        if (OUT == 1) { Cho = Ch + z * sC; Clo = Cl + z * sC; }
    }

    float acc[4][4][4];
#pragma unroll
    for (int i = 0; i < 4; i++)
#pragma unroll
        for (int j = 0; j < 4; j++)
#pragma unroll
            for (int l = 0; l < 4; l++) acc[i][j][l] = 0.f;

    const int lm_r = lane & 15;
    const int lm_c = (lane >> 4) << 3;
    const int tr_k = (lane & 7) | (((lane >> 3) & 1) << 3);
    const int tr_n = (lane >> 4) << 3;

    load_stage15<TRANSB, SPLIT_A, SPLIT_B>(sm, Abh, Abl, Bbh, Bbl, 0, K, N, tid);

    const int nT = K >> 5;
    for (int kt = 0; kt < nT; kt++) {
        asm volatile("cp.async.wait_group 0;");
        __syncthreads();
        if (kt + 1 < nT)
            load_stage15<TRANSB, SPLIT_A, SPLIT_B>(sm + ((kt + 1) & 1) * STAGE,
                                                   Abh, Abl, Bbh, Bbl,
                                                   (kt + 1) << 5, K, N, tid);

        __half* cs  = sm + (kt & 1) * STAGE;
        __half* sAh = cs;
        __half* sAl = cs + AE;
        __half* sBh = cs + AT;
        __half* sBl = cs + AT + BE;

#pragma unroll
        for (int ks = 0; ks < 2; ks++) {
            uint32_t af[4][4], bh[4][2], bl[4][2];

            if (TRANSB) {
#pragma unroll
                for (int h = 0; h < 2; h++) {
                    int row = wn * 32 + h * 16 + lm_r;
                    int col = ks * 16 + lm_c;
                    uint32_t t[4];
                    ldmx4(t, cvta_s(&sBh[row * LDB + col]));
                    bh[2 * h][0] = t[0]; bh[2 * h][1] = t[2];
                    bh[2 * h + 1][0] = t[1]; bh[2 * h + 1][1] = t[3];
                    if (SPLIT_B) {
                        ldmx4(t, cvta_s(&sBl[row * LDB + col]));
                        bl[2 * h][0] = t[0]; bl[2 * h][1] = t[2];
                        bl[2 * h + 1][0] = t[1]; bl[2 * h + 1][1] = t[3];
                    }
                }
            } else {
                int krow = ks * 16 + tr_k;
#pragma unroll
                for (int h = 0; h < 2; h++) {
                    int col = wn * 32 + h * 16 + tr_n;
                    uint32_t t[4];
                    ldmx4t(t, cvta_s(&sBh[krow * LDB + col]));
                    bh[2 * h][0] = t[0]; bh[2 * h][1] = t[1];
                    bh[2 * h + 1][0] = t[2]; bh[2 * h + 1][1] = t[3];
                    if (SPLIT_B) {
                        ldmx4t(t, cvta_s(&sBl[krow * LDB + col]));
                        bl[2 * h][0] = t[0]; bl[2 * h][1] = t[1];
                        bl[2 * h + 1][0] = t[2]; bl[2 * h + 1][1] = t[3];
                    }
                }
            }

            // pass 1 (+2): Ah*Bh (+ Ah*Bl)
#pragma unroll
            for (int mf = 0; mf < 4; mf++) {
                int row = wm * 64 + mf * 16 + lm_r;
                ldmx4(af[mf], cvta_s(&sAh[row * LDA + ks * 16 + lm_c]));
            }
#pragma unroll
            for (int mf = 0; mf < 4; mf++)
#pragma unroll
                for (int nf = 0; nf < 4; nf++) {
                    mma16816(acc[mf][nf], af[mf], bh[nf]);
                    if (SPLIT_B) mma16816(acc[mf][nf], af[mf], bl[nf]);
                }
            if (SPLIT_A) {
                // pass 3: Al*Bh
#pragma unroll
                for (int mf = 0; mf < 4; mf++) {
                    int row = wm * 64 + mf * 16 + lm_r;
                    ldmx4(af[mf], cvta_s(&sAl[row * LDA + ks * 16 + lm_c]));
                }
#pragma unroll
                for (int mf = 0; mf < 4; mf++)
#pragma unroll
                    for (int nf = 0; nf < 4; nf++)
                        mma16816(acc[mf][nf], af[mf], bh[nf]);
            }
        }
    }

    // ---- epilogue
    const int g  = lane >> 2;
    const int t2 = (lane & 3) << 1;

    if (OUT == 3) {
        // exp + un-normalized P (fp16) + atomic row sums
        __half* Chb = Ch + z * sC + (size_t)bm * N + bn;
        float rs[4][2];
#pragma unroll
        for (int mf = 0; mf < 4; mf++) { rs[mf][0] = 0.f; rs[mf][1] = 0.f; }
#pragma unroll
        for (int mf = 0; mf < 4; mf++) {
            int r0 = wm * 64 + mf * 16 + g;
#pragma unroll
            for (int nf = 0; nf < 4; nf++) {
                int c = wn * 32 + nf * 8 + t2;
                float e00 = fminf(__expf(acc[mf][nf][0] * alpha - EXPC), 60000.f);
                float e01 = fminf(__expf(acc[mf][nf][1] * alpha - EXPC), 60000.f);
                float e10 = fminf(__expf(acc[mf][nf][2] * alpha - EXPC), 60000.f);
                float e11 = fminf(__expf(acc[mf][nf][3] * alpha - EXPC), 60000.f);
                *(__half2*)(Chb + (size_t)r0 * N + c)       = hi2(e00, e01);
                *(__half2*)(Chb + (size_t)(r0 + 8) * N + c) = hi2(e10, e11);
                rs[mf][0] += e00 + e01;
                rs[mf][1] += e10 + e11;
            }
        }
#pragma unroll
        for (int mf = 0; mf < 4; mf++)
#pragma unroll
            for (int s = 0; s < 2; s++) {
                float v = rs[mf][s];
                v += __shfl_xor_sync(0xffffffffu, v, 1);
                v += __shfl_xor_sync(0xffffffffu, v, 2);
                rs[mf][s] = v;
            }
        float* rows = (float*)smraw;   // reuse stage smem (mainloop done)
        __syncthreads();
        if (tid < 128) rows[tid] = 0.f;
        __syncthreads();
        if ((lane & 3) == 0) {
#pragma unroll
            for (int mf = 0; mf < 4; mf++) {
                atomicAdd(&rows[wm * 64 + mf * 16 + g],     rs[mf][0]);
                atomicAdd(&rows[wm * 64 + mf * 16 + g + 8], rs[mf][1]);
            }
        }
        __syncthreads();
        if (tid < 128)
            atomicAdd(&rsum[(size_t)z * SEQ + bm + tid], rows[tid]);
        return;
    }

#pragma unroll
    for (int mf = 0; mf < 4; mf++) {
        int r0 = wm * 64 + mf * 16 + g;
        float sc0 = alpha, sc1 = alpha;
        if (OUT == 5) {
            sc0 = 1.f / rsum[(size_t)z * SEQ + bm + r0];
            sc1 = 1.f / rsum[(size_t)z * SEQ + bm + r0 + 8];
        }
#pragma unroll
        for (int nf = 0; nf < 4; nf++) {
            int c = wn * 32 + nf * 8 + t2;
            float bb0 = 0.f, bb1 = 0.f;
            if (bias) { bb0 = bias[bn + c]; bb1 = bias[bn + c + 1]; }
            float v00 = acc[mf][nf][0] * sc0 + bb0;
            float v01 = acc[mf][nf][1] * sc0 + bb1;
            float v10 = acc[mf][nf][2] * sc1 + bb0;
            float v11 = acc[mf][nf][3] * sc1 + bb1;
            if (OUT == 1) {
                __half* Chb = Cho + (size_t)bm * N + bn;
                __half* Clb = Clo + (size_t)bm * N + bn;
                __half2 h0 = hi2(v00, v01), h1 = hi2(v10, v11);
                __half2 L0 = lo2(v00, v01, h0), L1 = lo2(v10, v11, h1);
                *(__half2*)(Chb + (size_t)r0 * N + c)       = h0;
                *(__half2*)(Chb + (size_t)(r0 + 8) * N + c) = h1;
                *(__half2*)(Clb + (size_t)r0 * N + c)       = L0;
                *(__half2*)(Clb + (size_t)(r0 + 8) * N + c) = L1;
            } else if (OUT == 2) {
                __half* Chb = Ch + z * sC + (size_t)bm * N + bn;
                *(__half2*)(Chb + (size_t)r0 * N + c)       = hi2(v00, v01);
                *(__half2*)(Chb + (size_t)(r0 + 8) * N + c) = hi2(v10, v11);
            } else {
                float* Cfb = Cf + z * sC + (size_t)bm * N + bn;
                *(float2*)(Cfb + (size_t)r0 * N + c)       = make_float2(v00, v01);
                *(float2*)(Cfb + (size_t)(r0 + 8) * N + c) = make_float2(v10, v11);
            }
        }
    }
}

// ---------------------------------------------------------------------------
// merged elementwise split: x, Wq, Wk, Wv, Wo -> fp16 hi/lo; zeros R and BC.
// ---------------------------------------------------------------------------
constexpr int NX4 = (int)(NQ / 4);   // 2097152
constexpr int NW4 = (int)(NW / 4);   // 262144

__global__ __launch_bounds__(256)
void split_all(const float* __restrict__ x,
               const float* __restrict__ Wq, const float* __restrict__ Wk,
               const float* __restrict__ Wv, const float* __restrict__ Wo,
               __half* __restrict__ xh, __half* __restrict__ xl,
               __half* __restrict__ W3h, __half* __restrict__ W3l,
               __half* __restrict__ Woh, __half* __restrict__ Wol,
               float* __restrict__ R, float* __restrict__ BC)
{
    int i = blockIdx.x * blockDim.x + threadIdx.x;
    if (i < 2048) ((float4*)R)[i] = make_float4(0.f, 0.f, 0.f, 0.f);
    if (i < 256)  ((float4*)BC)[i] = make_float4(0.f, 0.f, 0.f, 0.f);

    const float* src;
    __half *dh, *dl;
    int o;
    if (i < NX4) {
        src = x; dh = xh; dl = xl; o = i;
    } else {
        int j = i - NX4;
        int r = j >> 18;            // / NW4
        o = j & (NW4 - 1);
        if      (r == 0) { src = Wq; dh = W3h;          dl = W3l; }
        else if (r == 1) { src = Wk; dh = W3h + NW;     dl = W3l + NW; }
        else if (r == 2) { src = Wv; dh = W3h + 2 * NW; dl = W3l + 2 * NW; }
        else             { src = Wo; dh = Woh;          dl = Wol; }
    }
    float4 v = ((const float4*)src)[o];
    __half2 h0 = hi2(v.x, v.y), h1 = hi2(v.z, v.w);
    __half2 l0 = lo2(v.x, v.y, h0), l1 = lo2(v.z, v.w, h1);
    ((__half2*)dh)[2 * o]     = h0;
    ((__half2*)dh)[2 * o + 1] = h1;
    ((__half2*)dl)[2 * o]     = l0;
    ((__half2*)dl)[2 * o + 1] = l1;
}

// bcomb[j] += partial sums of bv[d]*Wo[d][j]; bo added by the d-block 0.
// grid (DIM/256, 16), block 256. Coalesced Wo reads; BC pre-zeroed.
__global__ __launch_bounds__(256)
void bcomb_k(const float* __restrict__ bv, const float* __restrict__ Wo,
             const float* __restrict__ bo, float* __restrict__ bc)
{
    int j = blockIdx.x * 256 + threadIdx.x;
    int d0 = blockIdx.y * 64;
    float s = (blockIdx.y == 0) ? bo[j] : 0.f;
#pragma unroll 8
    for (int d = d0; d < d0 + 64; d++)
        s += bv[d] * Wo[(size_t)d * DIM + j];
    atomicAdd(&bc[j], s);
}

// ---------------------------------------------------------------------------
// kernel_launch
// ---------------------------------------------------------------------------
extern "C" void kernel_launch(void* const* d_in, const int* in_sizes, int n_in,
                              void* d_out, int out_size)
{
    const float* x  = (const float*)d_in[0];
    const float* Wq = (const float*)d_in[1];
    const float* bq = (const float*)d_in[2];
    const float* Wk = (const float*)d_in[3];
    const float* bk = (const float*)d_in[4];
    const float* Wv = (const float*)d_in[5];
    const float* bv = (const float*)d_in[6];
    const float* Wo = (const float*)d_in[7];
    const float* bo = (const float*)d_in[8];
    float* out = (float*)d_out;

    __half *xh, *xl, *W3h, *W3l, *Woh, *Wol, *QKVh, *QKVl, *U, *P;
    float *R, *BC;
    cudaGetSymbolAddress((void**)&xh, g_xh);     cudaGetSymbolAddress((void**)&xl, g_xl);
    cudaGetSymbolAddress((void**)&W3h, g_W3h);   cudaGetSymbolAddress((void**)&W3l, g_W3l);
    cudaGetSymbolAddress((void**)&Woh, g_Woh);   cudaGetSymbolAddress((void**)&Wol, g_Wol);
    cudaGetSymbolAddress((void**)&QKVh, g_QKVh); cudaGetSymbolAddress((void**)&QKVl, g_QKVl);
    cudaGetSymbolAddress((void**)&U, g_O);       cudaGetSymbolAddress((void**)&P, g_P);
    cudaGetSymbolAddress((void**)&R, g_R);       cudaGetSymbolAddress((void**)&BC, g_BC);

    __half* Wvoh = QKVh + 2 * NQ;   // Wvo hi (old V slot)
    __half* Wvol = QKVl + 2 * NQ;   // Wvo lo scratch (unused downstream)

    // dynamic smem bytes (2 stages)
    const int SM_PROJ = 2 * 2 * (2 * 128 * LDA + 2 * 32 * LDB_NN);  // 75776
    const int SM_SC2  = 2 * 2 * (128 * LDA + 2 * 128 * LDA);        // 61440
    const int SM_1P   = 2 * 2 * (128 * LDA + 32 * LDB_NN);          // 37888
    cudaFuncSetAttribute(gemm15<false, true,  true,  1>, cudaFuncAttributeMaxDynamicSharedMemorySize, SM_PROJ);
    cudaFuncSetAttribute(gemm15<true,  false, true,  3>, cudaFuncAttributeMaxDynamicSharedMemorySize, SM_SC2);
    cudaFuncSetAttribute(gemm15<false, false, false, 2>, cudaFuncAttributeMaxDynamicSharedMemorySize, SM_1P);
    cudaFuncSetAttribute(gemm15<false, false, false, 5>, cudaFuncAttributeMaxDynamicSharedMemorySize, SM_1P);

    const int M = BATCH * SEQ;          // 8192
    const float scale = 0.125f;         // 1/sqrt(64)
    dim3 b256(256);
    const size_t sQ = (size_t)SEQ * DIM;

    // merged pre-split (x, Wq, Wk, Wv, Wo -> hi/lo) + zero R, BC
    split_all<<<(NX4 + 4 * NW4) / 256, b256>>>(x, Wq, Wk, Wv, Wo,
                                               xh, xl, W3h, W3l, Woh, Wol, R, BC);

    // bcomb = bv @ Wo + bo (parallel partial sums)
    dim3 gBC(DIM / 256, 16);
    bcomb_k<<<gBC, b256>>>(bv, Wo, bo, BC);

    // QK projection + Wvo, one launch: z in {0,1} -> Q,K (3-pass, split out);
    // z == 2 -> Wvo = Wv @ Wo (3-pass, split out to Wvoh/Wvol, 8 y-blocks)
    dim3 gQK(DIM / 128, M / 128, 3);
    gemm15<false, true, true, 1><<<gQK, b256, SM_PROJ>>>(
        xh, xl, W3h, W3l, nullptr, QKVh, QKVl, bq, bk, nullptr, nullptr,
        W3h + 2 * NW, W3l + 2 * NW, Woh, Wol, Wvoh, Wvol,
        DIM, DIM, 1.f, 0, NW, NQ);

    // U = x @ Wvo (1-pass, single fp16 out, no bias)
    dim3 gU(DIM / 128, M / 128, 1);
    gemm15<false, false, false, 2><<<gU, b256, SM_1P>>>(
        xh, nullptr, Wvoh, nullptr, nullptr, U, nullptr,
        nullptr, nullptr, nullptr, nullptr,
        nullptr, nullptr, nullptr, nullptr, nullptr, nullptr,
        DIM, DIM, 1.f, 0, 0, 0);

    __half *Qh = QKVh;
    __half *Kh = QKVh + NQ, *Kl = QKVl + NQ;

    // scores + fused exp (2-pass: Qh*Kh + Qh*Kl): P = fp16(exp(scale*QK^T-18)), R += row sums
    dim3 gScore(SEQ / 128, SEQ / 128, BATCH);
    gemm15<true, false, true, 3><<<gScore, b256, SM_SC2>>>(
        Qh, nullptr, Kh, Kl, nullptr, P, nullptr, nullptr, nullptr, nullptr, R,
        nullptr, nullptr, nullptr, nullptr, nullptr, nullptr,
        SEQ, DIM, scale, sQ, sQ, (size_t)SEQ * SEQ);

    // out = (P @ U) / R[row] + bcomb (1-pass, fp32 out), z = batch; sB = sQ!
    dim3 gPV(DIM / 128, SEQ / 128, BATCH);
    gemm15<false, false, false, 5><<<gPV, b256, SM_1P>>>(
        P, nullptr, U, nullptr, out, nullptr, nullptr,
        BC, BC, nullptr, R,
        nullptr, nullptr, nullptr, nullptr, nullptr, nullptr,
        DIM, SEQ, 1.f, (size_t)SEQ * SEQ, sQ, sQ);
}

// round 16
// speedup vs baseline: 1.0735x; 1.0228x over previous
#include <cuda_runtime.h>
#include <cuda_fp16.h>
#include <math.h>
#include <stdint.h>

#define BATCH 2
#define SEQ   4096
#define DIM   1024

#define NQ  ((size_t)BATCH * SEQ * DIM)
#define NP  ((size_t)BATCH * SEQ * SEQ)
#define NW  ((size_t)DIM * DIM)

// ---- device scratch ----
__device__ __half g_xh[NQ],  g_xl[NQ];
__device__ __half g_W3h[3 * NW], g_W3l[3 * NW];   // Wq|Wk|Wv stacked (hi/lo)
__device__ __half g_Woh[NW], g_Wol[NW];
__device__ __half g_QKVh[3 * NQ], g_QKVl[3 * NQ]; // Q|K split; slot 2: Wvo hi / scratch lo
__device__ __half g_O[NQ];                         // U = x @ Wvo, fp16
__device__ __half g_P[NP];                         // un-normalized probs exp(s-18), fp16
__device__ float  g_R[(size_t)BATCH * SEQ];        // row sums of exp(s-18)
__device__ float  g_BC[DIM];                       // bcomb = bv@Wo + bo

// ---------------------------------------------------------------------------
// PTX helpers
// ---------------------------------------------------------------------------
__device__ __forceinline__ uint32_t cvta_s(const void* p) {
    return (uint32_t)__cvta_generic_to_shared(p);
}
__device__ __forceinline__ void cp16(uint32_t dst, const void* src) {
    asm volatile("cp.async.cg.shared.global [%0], [%1], 16;" :: "r"(dst), "l"(src));
}
__device__ __forceinline__ void ldmx4(uint32_t* r, uint32_t a) {
    asm volatile("ldmatrix.sync.aligned.m8n8.x4.shared.b16 {%0,%1,%2,%3}, [%4];"
                 : "=r"(r[0]), "=r"(r[1]), "=r"(r[2]), "=r"(r[3]) : "r"(a));
}
__device__ __forceinline__ void ldmx4t(uint32_t* r, uint32_t a) {
    asm volatile("ldmatrix.sync.aligned.m8n8.x4.trans.shared.b16 {%0,%1,%2,%3}, [%4];"
                 : "=r"(r[0]), "=r"(r[1]), "=r"(r[2]), "=r"(r[3]) : "r"(a));
}
__device__ __forceinline__ void mma16816(float* c, const uint32_t* a, const uint32_t* b) {
    asm volatile(
        "mma.sync.aligned.m16n8k16.row.col.f32.f16.f16.f32 "
        "{%0,%1,%2,%3}, {%4,%5,%6,%7}, {%8,%9}, {%0,%1,%2,%3};"
        : "+f"(c[0]), "+f"(c[1]), "+f"(c[2]), "+f"(c[3])
        : "r"(a[0]), "r"(a[1]), "r"(a[2]), "r"(a[3]), "r"(b[0]), "r"(b[1]));
}
__device__ __forceinline__ __half2 hi2(float a, float b) {
    return __floats2half2_rn(a, b);
}
__device__ __forceinline__ __half2 lo2(float a, float b, __half2 h) {
    return __floats2half2_rn(a - __half2float(__low2half(h)),
                             b - __half2float(__high2half(h)));
}

// ---------------------------------------------------------------------------
// Split-fp16 GEMM (R7/R9 structure, mainloop UNchanged): CTA 128x128, BK=32,
// 256 thr, warps 2x4, warp tile 64x32, 2-stage cp.async.
//   passes: Ah*Bh [+ Ah*Bl if SPLIT_B] [+ Al*Bh if SPLIT_A]
//   OUT: 1 = split fp16 hi/lo(+bias), 2 = single fp16(+bias),
//        3 = exp epilogue: P=fp16(exp(alpha*acc-18)) + atomic row sums,
//        5 = fp32, scaled by 1/rsum[z*SEQ+row], +bias.
//   OUT==1 with z==2: alternate operands (A2,B2 -> C2), 8 valid y-blocks.
// ---------------------------------------------------------------------------
constexpr int LDA    = 40;   // 32 + 8 pad
constexpr int LDB_NN = 136;  // 128 + 8 pad
constexpr float EXPC = 18.0f;

template <bool TRANSB, bool SPLIT_A, bool SPLIT_B>
__device__ __forceinline__ void load_stage16(
    __half* sb,
    const __half* Ah, const __half* Al,
    const __half* Bh, const __half* Bl,
    int k0, int K, int N, int tid)
{
    constexpr int AE = 128 * LDA;                        // 5120
    constexpr int AT = SPLIT_A ? 2 * AE : AE;
    constexpr int BE = TRANSB ? 128 * LDA : 32 * LDB_NN; // 5120 / 4352
    __half* sAh = sb;
    __half* sAl = sb + AE;
    __half* sBh = sb + AT;
    __half* sBl = sb + AT + BE;

#pragma unroll
    for (int i = 0; i < 2; i++) {
        int c = tid + (i << 8);
        int row = c >> 2, col = (c & 3) << 3;
        size_t g = (size_t)row * K + k0 + col;
        uint32_t so = row * LDA + col;
        cp16(cvta_s(sAh + so), Ah + g);
        if (SPLIT_A) cp16(cvta_s(sAl + so), Al + g);
    }
    if (TRANSB) {
#pragma unroll
        for (int i = 0; i < 2; i++) {
            int c = tid + (i << 8);
            int row = c >> 2, col = (c & 3) << 3;
            size_t g = (size_t)row * K + k0 + col;
            uint32_t so = row * LDA + col;
            cp16(cvta_s(sBh + so), Bh + g);
            if (SPLIT_B) cp16(cvta_s(sBl + so), Bl + g);
        }
    } else {
#pragma unroll
        for (int i = 0; i < 2; i++) {
            int c = tid + (i << 8);
            int row = c >> 4, col = (c & 15) << 3;
            size_t g = (size_t)(k0 + row) * N + col;
            uint32_t so = row * LDB_NN + col;
            cp16(cvta_s(sBh + so), Bh + g);
            if (SPLIT_B) cp16(cvta_s(sBl + so), Bl + g);
        }
    }
    asm volatile("cp.async.commit_group;");
}

template <bool TRANSB, bool SPLIT_A, bool SPLIT_B, int OUT>
__global__ __launch_bounds__(256, 2)
void gemm16(const __half* __restrict__ Agh, const __half* __restrict__ Agl,
            const __half* __restrict__ Bgh, const __half* __restrict__ Bgl,
            float* __restrict__ Cf,
            __half* __restrict__ Ch, __half* __restrict__ Cl,
            const float* __restrict__ b0, const float* __restrict__ b1,
            const float* __restrict__ b2,
            float* __restrict__ rsum,
            const __half* __restrict__ A2h, const __half* __restrict__ A2l,
            const __half* __restrict__ B2h, const __half* __restrict__ B2l,
            __half* __restrict__ C2h, __half* __restrict__ C2l,
            int N, int K, float alpha,
            size_t sA, size_t sB, size_t sC)
{
    extern __shared__ __align__(16) char smraw[];
    __half* sm = (__half*)smraw;
    constexpr int AE    = 128 * LDA;
    constexpr int AT    = SPLIT_A ? 2 * AE : AE;
    constexpr int BE    = TRANSB ? 128 * LDA : 32 * LDB_NN;
    constexpr int BT    = SPLIT_B ? 2 * BE : BE;
    constexpr int STAGE = AT + BT;
    constexpr int LDB   = TRANSB ? LDA : LDB_NN;

    const int tid  = threadIdx.x;
    const int lane = tid & 31;
    const int warp = tid >> 5;
    const int wm   = warp & 1;    // 2 row groups of 64
    const int wn   = warp >> 1;   // 4 col groups of 32
    const int z    = blockIdx.z;
    const int bm = blockIdx.y << 7, bn = blockIdx.x << 7;

    const float* bias = (z == 0) ? b0 : (z == 1) ? b1 : b2;

    const __half *Abh, *Abl = nullptr, *Bbh, *Bbl = nullptr;
    __half *Cho = nullptr, *Clo = nullptr;   // OUT==1 destinations

    if (OUT == 1 && z == 2) {
        // Wvo slice: A = Wv (hi/lo) [1024,K], B = Wo (hi/lo) [K,N] NN
        if (blockIdx.y >= 8) return;
        Abh = A2h + (size_t)bm * K;
        Abl = A2l + (size_t)bm * K;
        Bbh = B2h + bn;
        Bbl = B2l + bn;
        Cho = C2h;
        Clo = C2l;
    } else {
        Abh = Agh + z * sA + (size_t)bm * K;
        if (SPLIT_A) Abl = Agl + z * sA + (size_t)bm * K;
        if (TRANSB) {
            Bbh = Bgh + z * sB + (size_t)bn * K;
            if (SPLIT_B) Bbl = Bgl + z * sB + (size_t)bn * K;
        } else {
            Bbh = Bgh + z * sB + bn;
            if (SPLIT_B) Bbl = Bgl + z * sB + bn;
        }
        if (OUT == 1) { Cho = Ch + z * sC; Clo = Cl + z * sC; }
    }

    float acc[4][4][4];
#pragma unroll
    for (int i = 0; i < 4; i++)
#pragma unroll
        for (int j = 0; j < 4; j++)
#pragma unroll
            for (int l = 0; l < 4; l++) acc[i][j][l] = 0.f;

    const int lm_r = lane & 15;
    const int lm_c = (lane >> 4) << 3;
    const int tr_k = (lane & 7) | (((lane >> 3) & 1) << 3);
    const int tr_n = (lane >> 4) << 3;

    load_stage16<TRANSB, SPLIT_A, SPLIT_B>(sm, Abh, Abl, Bbh, Bbl, 0, K, N, tid);

    const int nT = K >> 5;
    for (int kt = 0; kt < nT; kt++) {
        asm volatile("cp.async.wait_group 0;");
        __syncthreads();
        if (kt + 1 < nT)
            load_stage16<TRANSB, SPLIT_A, SPLIT_B>(sm + ((kt + 1) & 1) * STAGE,
                                                   Abh, Abl, Bbh, Bbl,
                                                   (kt + 1) << 5, K, N, tid);

        __half* cs  = sm + (kt & 1) * STAGE;
        __half* sAh = cs;
        __half* sAl = cs + AE;
        __half* sBh = cs + AT;
        __half* sBl = cs + AT + BE;

#pragma unroll
        for (int ks = 0; ks < 2; ks++) {
            uint32_t af[4][4], bh[4][2], bl[4][2];

            if (TRANSB) {
#pragma unroll
                for (int h = 0; h < 2; h++) {
                    int row = wn * 32 + h * 16 + lm_r;
                    int col = ks * 16 + lm_c;
                    uint32_t t[4];
                    ldmx4(t, cvta_s(&sBh[row * LDB + col]));
                    bh[2 * h][0] = t[0]; bh[2 * h][1] = t[2];
                    bh[2 * h + 1][0] = t[1]; bh[2 * h + 1][1] = t[3];
                    if (SPLIT_B) {
                        ldmx4(t, cvta_s(&sBl[row * LDB + col]));
                        bl[2 * h][0] = t[0]; bl[2 * h][1] = t[2];
                        bl[2 * h + 1][0] = t[1]; bl[2 * h + 1][1] = t[3];
                    }
                }
            } else {
                int krow = ks * 16 + tr_k;
#pragma unroll
                for (int h = 0; h < 2; h++) {
                    int col = wn * 32 + h * 16 + tr_n;
                    uint32_t t[4];
                    ldmx4t(t, cvta_s(&sBh[krow * LDB + col]));
                    bh[2 * h][0] = t[0]; bh[2 * h][1] = t[1];
                    bh[2 * h + 1][0] = t[2]; bh[2 * h + 1][1] = t[3];
                    if (SPLIT_B) {
                        ldmx4t(t, cvta_s(&sBl[krow * LDB + col]));
                        bl[2 * h][0] = t[0]; bl[2 * h][1] = t[1];
                        bl[2 * h + 1][0] = t[2]; bl[2 * h + 1][1] = t[3];
                    }
                }
            }

            // pass 1 (+2): Ah*Bh (+ Ah*Bl)
#pragma unroll
            for (int mf = 0; mf < 4; mf++) {
                int row = wm * 64 + mf * 16 + lm_r;
                ldmx4(af[mf], cvta_s(&sAh[row * LDA + ks * 16 + lm_c]));
            }
#pragma unroll
            for (int mf = 0; mf < 4; mf++)
#pragma unroll
                for (int nf = 0; nf < 4; nf++) {
                    mma16816(acc[mf][nf], af[mf], bh[nf]);
                    if (SPLIT_B) mma16816(acc[mf][nf], af[mf], bl[nf]);
                }
            if (SPLIT_A) {
                // pass 3: Al*Bh
#pragma unroll
                for (int mf = 0; mf < 4; mf++) {
                    int row = wm * 64 + mf * 16 + lm_r;
                    ldmx4(af[mf], cvta_s(&sAl[row * LDA + ks * 16 + lm_c]));
                }
#pragma unroll
                for (int mf = 0; mf < 4; mf++)
#pragma unroll
                    for (int nf = 0; nf < 4; nf++)
                        mma16816(acc[mf][nf], af[mf], bh[nf]);
            }
        }
    }

    // ---- epilogue
    const int g  = lane >> 2;
    const int t2 = (lane & 3) << 1;

    if (OUT == 3) {
        // exp + un-normalized P (fp16) + atomic row sums
        __half* Chb = Ch + z * sC + (size_t)bm * N + bn;
        float rs[4][2];
#pragma unroll
        for (int mf = 0; mf < 4; mf++) { rs[mf][0] = 0.f; rs[mf][1] = 0.f; }
#pragma unroll
        for (int mf = 0; mf < 4; mf++) {
            int r0 = wm * 64 + mf * 16 + g;
#pragma unroll
            for (int nf = 0; nf < 4; nf++) {
                int c = wn * 32 + nf * 8 + t2;
                float e00 = fminf(__expf(acc[mf][nf][0] * alpha - EXPC), 60000.f);
                float e01 = fminf(__expf(acc[mf][nf][1] * alpha - EXPC), 60000.f);
                float e10 = fminf(__expf(acc[mf][nf][2] * alpha - EXPC), 60000.f);
                float e11 = fminf(__expf(acc[mf][nf][3] * alpha - EXPC), 60000.f);
                *(__half2*)(Chb + (size_t)r0 * N + c)       = hi2(e00, e01);
                *(__half2*)(Chb + (size_t)(r0 + 8) * N + c) = hi2(e10, e11);
                rs[mf][0] += e00 + e01;
                rs[mf][1] += e10 + e11;
            }
        }
#pragma unroll
        for (int mf = 0; mf < 4; mf++)
#pragma unroll
            for (int s = 0; s < 2; s++) {
                float v = rs[mf][s];
                v += __shfl_xor_sync(0xffffffffu, v, 1);
                v += __shfl_xor_sync(0xffffffffu, v, 2);
                rs[mf][s] = v;
            }
        float* rows = (float*)smraw;   // reuse stage smem (mainloop done)
        __syncthreads();
        if (tid < 128) rows[tid] = 0.f;
        __syncthreads();
        if ((lane & 3) == 0) {
#pragma unroll
            for (int mf = 0; mf < 4; mf++) {
                atomicAdd(&rows[wm * 64 + mf * 16 + g],     rs[mf][0]);
                atomicAdd(&rows[wm * 64 + mf * 16 + g + 8], rs[mf][1]);
            }
        }
        __syncthreads();
        if (tid < 128)
            atomicAdd(&rsum[(size_t)z * SEQ + bm + tid], rows[tid]);
        return;
    }

#pragma unroll
    for (int mf = 0; mf < 4; mf++) {
        int r0 = wm * 64 + mf * 16 + g;
        float sc0 = alpha, sc1 = alpha;
        if (OUT == 5) {
            sc0 = 1.f / rsum[(size_t)z * SEQ + bm + r0];
            sc1 = 1.f / rsum[(size_t)z * SEQ + bm + r0 + 8];
        }
#pragma unroll
        for (int nf = 0; nf < 4; nf++) {
            int c = wn * 32 + nf * 8 + t2;
            float bb0 = 0.f, bb1 = 0.f;
            if (bias) { bb0 = bias[bn + c]; bb1 = bias[bn + c + 1]; }
            float v00 = acc[mf][nf][0] * sc0 + bb0;
            float v01 = acc[mf][nf][1] * sc0 + bb1;
            float v10 = acc[mf][nf][2] * sc1 + bb0;
            float v11 = acc[mf][nf][3] * sc1 + bb1;
            if (OUT == 1) {
                __half* Chb = Cho + (size_t)bm * N + bn;
                __half* Clb = Clo + (size_t)bm * N + bn;
                __half2 h0 = hi2(v00, v01), h1 = hi2(v10, v11);
                __half2 L0 = lo2(v00, v01, h0), L1 = lo2(v10, v11, h1);
                *(__half2*)(Chb + (size_t)r0 * N + c)       = h0;
                *(__half2*)(Chb + (size_t)(r0 + 8) * N + c) = h1;
                *(__half2*)(Clb + (size_t)r0 * N + c)       = L0;
                *(__half2*)(Clb + (size_t)(r0 + 8) * N + c) = L1;
            } else if (OUT == 2) {
                __half* Chb = Ch + z * sC + (size_t)bm * N + bn;
                *(__half2*)(Chb + (size_t)r0 * N + c)       = hi2(v00, v01);
                *(__half2*)(Chb + (size_t)(r0 + 8) * N + c) = hi2(v10, v11);
            } else {
                float* Cfb = Cf + z * sC + (size_t)bm * N + bn;
                *(float2*)(Cfb + (size_t)r0 * N + c)       = make_float2(v00, v01);
                *(float2*)(Cfb + (size_t)(r0 + 8) * N + c) = make_float2(v10, v11);
            }
        }
    }
}

// ---------------------------------------------------------------------------
// merged elementwise split: x, Wq, Wk, Wv, Wo -> fp16 hi/lo; zeros R.
// (BC is NOT zeroed here — bcomb_k writes it directly on the side stream.)
// ---------------------------------------------------------------------------
constexpr int NX4 = (int)(NQ / 4);   // 2097152
constexpr int NW4 = (int)(NW / 4);   // 262144

__global__ __launch_bounds__(256)
void split_all(const float* __restrict__ x,
               const float* __restrict__ Wq, const float* __restrict__ Wk,
               const float* __restrict__ Wv, const float* __restrict__ Wo,
               __half* __restrict__ xh, __half* __restrict__ xl,
               __half* __restrict__ W3h, __half* __restrict__ W3l,
               __half* __restrict__ Woh, __half* __restrict__ Wol,
               float* __restrict__ R)
{
    int i = blockIdx.x * blockDim.x + threadIdx.x;
    if (i < 2048) ((float4*)R)[i] = make_float4(0.f, 0.f, 0.f, 0.f);

    const float* src;
    __half *dh, *dl;
    int o;
    if (i < NX4) {
        src = x; dh = xh; dl = xl; o = i;
    } else {
        int j = i - NX4;
        int r = j >> 18;            // / NW4
        o = j & (NW4 - 1);
        if      (r == 0) { src = Wq; dh = W3h;          dl = W3l; }
        else if (r == 1) { src = Wk; dh = W3h + NW;     dl = W3l + NW; }
        else if (r == 2) { src = Wv; dh = W3h + 2 * NW; dl = W3l + 2 * NW; }
        else             { src = Wo; dh = Woh;          dl = Wol; }
    }
    float4 v = ((const float4*)src)[o];
    __half2 h0 = hi2(v.x, v.y), h1 = hi2(v.z, v.w);
    __half2 l0 = lo2(v.x, v.y, h0), l1 = lo2(v.z, v.w, h1);
    ((__half2*)dh)[2 * o]     = h0;
    ((__half2*)dh)[2 * o + 1] = h1;
    ((__half2*)dl)[2 * o]     = l0;
    ((__half2*)dl)[2 * o + 1] = l1;
}

// bcomb[j] = sum_d bv[d]*Wo[d][j] + bo[j].  Single-shot, no atomics.
// grid (DIM/256), block 256; coalesced Wo reads. Runs on the side stream
// overlapped with split_all/QK (reads only raw harness inputs).
__global__ __launch_bounds__(256)
void bcomb_k(const float* __restrict__ bv, const float* __restrict__ Wo,
             const float* __restrict__ bo, float* __restrict__ bc)
{
    int j = blockIdx.x * 256 + threadIdx.x;
    float s = bo[j];
#pragma unroll 4
    for (int d = 0; d < DIM; d++)
        s += bv[d] * Wo[(size_t)d * DIM + j];
    bc[j] = s;
}

// ---------------------------------------------------------------------------
// kernel_launch — forked-stream capture: side stream runs bcomb + U GEMM.
// ---------------------------------------------------------------------------
extern "C" void kernel_launch(void* const* d_in, const int* in_sizes, int n_in,
                              void* d_out, int out_size)
{
    const float* x  = (const float*)d_in[0];
    const float* Wq = (const float*)d_in[1];
    const float* bq = (const float*)d_in[2];
    const float* Wk = (const float*)d_in[3];
    const float* bk = (const float*)d_in[4];
    const float* Wv = (const float*)d_in[5];
    const float* bv = (const float*)d_in[6];
    const float* Wo = (const float*)d_in[7];
    const float* bo = (const float*)d_in[8];
    float* out = (float*)d_out;

    __half *xh, *xl, *W3h, *W3l, *Woh, *Wol, *QKVh, *QKVl, *U, *P;
    float *R, *BC;
    cudaGetSymbolAddress((void**)&xh, g_xh);     cudaGetSymbolAddress((void**)&xl, g_xl);
    cudaGetSymbolAddress((void**)&W3h, g_W3h);   cudaGetSymbolAddress((void**)&W3l, g_W3l);
    cudaGetSymbolAddress((void**)&Woh, g_Woh);   cudaGetSymbolAddress((void**)&Wol, g_Wol);
    cudaGetSymbolAddress((void**)&QKVh, g_QKVh); cudaGetSymbolAddress((void**)&QKVl, g_QKVl);
    cudaGetSymbolAddress((void**)&U, g_O);       cudaGetSymbolAddress((void**)&P, g_P);
    cudaGetSymbolAddress((void**)&R, g_R);       cudaGetSymbolAddress((void**)&BC, g_BC);

    __half* Wvoh = QKVh + 2 * NQ;   // Wvo hi (old V slot)
    __half* Wvol = QKVl + 2 * NQ;   // Wvo lo scratch (unused downstream)

    // dynamic smem bytes (2 stages)
    const int SM_PROJ = 2 * 2 * (2 * 128 * LDA + 2 * 32 * LDB_NN);  // 75776
    const int SM_SC2  = 2 * 2 * (128 * LDA + 2 * 128 * LDA);        // 61440
    const int SM_1P   = 2 * 2 * (128 * LDA + 32 * LDB_NN);          // 37888
    cudaFuncSetAttribute(gemm16<false, true,  true,  1>, cudaFuncAttributeMaxDynamicSharedMemorySize, SM_PROJ);
    cudaFuncSetAttribute(gemm16<true,  false, true,  3>, cudaFuncAttributeMaxDynamicSharedMemorySize, SM_SC2);
    cudaFuncSetAttribute(gemm16<false, false, false, 2>, cudaFuncAttributeMaxDynamicSharedMemorySize, SM_1P);
    cudaFuncSetAttribute(gemm16<false, false, false, 5>, cudaFuncAttributeMaxDynamicSharedMemorySize, SM_1P);

    const int M = BATCH * SEQ;          // 8192
    const float scale = 0.125f;         // 1/sqrt(64)
    dim3 b256(256);
    const size_t sQ = (size_t)SEQ * DIM;

    // side stream + events (created per call; few calls total, capture-safe)
    cudaStream_t s2;
    cudaStreamCreate(&s2);
    cudaEvent_t ev0, evA, evU;
    cudaEventCreateWithFlags(&ev0, cudaEventDisableTiming);
    cudaEventCreateWithFlags(&evA, cudaEventDisableTiming);
    cudaEventCreateWithFlags(&evU, cudaEventDisableTiming);

    // fork: side stream joins at the start
    cudaEventRecord(ev0, 0);
    cudaStreamWaitEvent(s2, ev0, 0);

    // side: bcomb (inputs only) — hidden under split_all + QK
    bcomb_k<<<DIM / 256, b256, 0, s2>>>(bv, Wo, bo, BC);

    // main: merged pre-split (x, Wq, Wk, Wv, Wo -> hi/lo) + zero R
    split_all<<<(NX4 + 4 * NW4) / 256, b256>>>(x, Wq, Wk, Wv, Wo,
                                               xh, xl, W3h, W3l, Woh, Wol, R);

    // main: QK projection + Wvo, one launch (z in {0,1} -> Q,K; z==2 -> Wvo)
    dim3 gQK(DIM / 128, M / 128, 3);
    gemm16<false, true, true, 1><<<gQK, b256, SM_PROJ>>>(
        xh, xl, W3h, W3l, nullptr, QKVh, QKVl, bq, bk, nullptr, nullptr,
        W3h + 2 * NW, W3l + 2 * NW, Woh, Wol, Wvoh, Wvol,
        DIM, DIM, 1.f, 0, NW, NQ);
    cudaEventRecord(evA, 0);

    // side: U = x @ Wvo (1-pass) — overlaps the scores launch
    cudaStreamWaitEvent(s2, evA, 0);
    dim3 gU(DIM / 128, M / 128, 1);
    gemm16<false, false, false, 2><<<gU, b256, SM_1P, s2>>>(
        xh, nullptr, Wvoh, nullptr, nullptr, U, nullptr,
        nullptr, nullptr, nullptr, nullptr,
        nullptr, nullptr, nullptr, nullptr, nullptr, nullptr,
        DIM, DIM, 1.f, 0, 0, 0);
    cudaEventRecord(evU, s2);

    __half *Qh = QKVh;
    __half *Kh = QKVh + NQ, *Kl = QKVl + NQ;

    // main: scores + fused exp (2-pass): P = fp16(exp(scale*QK^T-18)), R += sums
    dim3 gScore(SEQ / 128, SEQ / 128, BATCH);
    gemm16<true, false, true, 3><<<gScore, b256, SM_SC2>>>(
        Qh, nullptr, Kh, Kl, nullptr, P, nullptr, nullptr, nullptr, nullptr, R,
        nullptr, nullptr, nullptr, nullptr, nullptr, nullptr,
        SEQ, DIM, scale, sQ, sQ, (size_t)SEQ * SEQ);

    // join: PV needs U (side) + P,R (main) + BC (side)
    cudaStreamWaitEvent(0, evU, 0);

    // main: out = (P @ U) / R[row] + bcomb (1-pass, fp32 out), z = batch
    dim3 gPV(DIM / 128, SEQ / 128, BATCH);
    gemm16<false, false, false, 5><<<gPV, b256, SM_1P>>>(
        P, nullptr, U, nullptr, out, nullptr, nullptr,
        BC, BC, nullptr, R,
        nullptr, nullptr, nullptr, nullptr, nullptr, nullptr,
        DIM, SEQ, 1.f, (size_t)SEQ * SEQ, sQ, sQ);
}

// round 17
// speedup vs baseline: 1.0869x; 1.0124x over previous
#include <cuda_runtime.h>
#include <cuda_fp16.h>
#include <math.h>
#include <stdint.h>

#define BATCH 2
#define SEQ   4096
#define DIM   1024

#define NQ  ((size_t)BATCH * SEQ * DIM)
#define NP  ((size_t)BATCH * SEQ * SEQ)
#define NW  ((size_t)DIM * DIM)

// ---- device scratch ----
__device__ __half g_xh[NQ],  g_xl[NQ];
__device__ __half g_W3h[3 * NW], g_W3l[3 * NW];   // Wq|Wk|Wv stacked (hi/lo)
__device__ __half g_Woh[NW], g_Wol[NW];
__device__ __half g_QKVh[3 * NQ], g_QKVl[3 * NQ]; // Q|K split; slot 2: Wvo hi / scratch lo
__device__ __half g_O[NQ];                         // U = x @ Wvo, fp16
__device__ __half g_P[NP];                         // un-normalized probs exp(s-18), fp16
__device__ float  g_R[(size_t)BATCH * SEQ];        // row sums of exp(s-18)
__device__ float  g_BC[DIM];                       // bcomb = bv@Wo + bo

// ---------------------------------------------------------------------------
// PTX helpers
// ---------------------------------------------------------------------------
__device__ __forceinline__ uint32_t cvta_s(const void* p) {
    return (uint32_t)__cvta_generic_to_shared(p);
}
__device__ __forceinline__ void cp16(uint32_t dst, const void* src) {
    asm volatile("cp.async.cg.shared.global [%0], [%1], 16;" :: "r"(dst), "l"(src));
}
__device__ __forceinline__ void ldmx4(uint32_t* r, uint32_t a) {
    asm volatile("ldmatrix.sync.aligned.m8n8.x4.shared.b16 {%0,%1,%2,%3}, [%4];"
                 : "=r"(r[0]), "=r"(r[1]), "=r"(r[2]), "=r"(r[3]) : "r"(a));
}
__device__ __forceinline__ void ldmx4t(uint32_t* r, uint32_t a) {
    asm volatile("ldmatrix.sync.aligned.m8n8.x4.trans.shared.b16 {%0,%1,%2,%3}, [%4];"
                 : "=r"(r[0]), "=r"(r[1]), "=r"(r[2]), "=r"(r[3]) : "r"(a));
}
__device__ __forceinline__ void mma16816(float* c, const uint32_t* a, const uint32_t* b) {
    asm volatile(
        "mma.sync.aligned.m16n8k16.row.col.f32.f16.f16.f32 "
        "{%0,%1,%2,%3}, {%4,%5,%6,%7}, {%8,%9}, {%0,%1,%2,%3};"
        : "+f"(c[0]), "+f"(c[1]), "+f"(c[2]), "+f"(c[3])
        : "r"(a[0]), "r"(a[1]), "r"(a[2]), "r"(a[3]), "r"(b[0]), "r"(b[1]));
}
__device__ __forceinline__ __half2 hi2(float a, float b) {
    return __floats2half2_rn(a, b);
}
__device__ __forceinline__ __half2 lo2(float a, float b, __half2 h) {
    return __floats2half2_rn(a - __half2float(__low2half(h)),
                             b - __half2float(__high2half(h)));
}

// ---------------------------------------------------------------------------
// Split-fp16 GEMM (R7/R9 structure, mainloop UNchanged): CTA 128x128, BK=32,
// 256 thr, warps 2x4, warp tile 64x32, 2-stage cp.async.
//   passes: Ah*Bh [+ Ah*Bl if SPLIT_B] [+ Al*Bh if SPLIT_A]
//   OUT: 1 = split fp16 hi/lo(+bias), 2 = single fp16(+bias),
//        3 = exp epilogue: P=fp16(exp(alpha*acc-18)) + atomic row sums,
//        5 = fp32, scaled by 1/rsum[z*SEQ+row], +bias.
//   OUT==1 with z==2: alternate operands (A2,B2 -> C2), 8 valid y-blocks.
// ---------------------------------------------------------------------------
constexpr int LDA    = 40;   // 32 + 8 pad
constexpr int LDB_NN = 136;  // 128 + 8 pad
constexpr float EXPC = 18.0f;

template <bool TRANSB, bool SPLIT_A, bool SPLIT_B>
__device__ __forceinline__ void load_stage17(
    __half* sb,
    const __half* Ah, const __half* Al,
    const __half* Bh, const __half* Bl,
    int k0, int K, int N, int tid)
{
    constexpr int AE = 128 * LDA;                        // 5120
    constexpr int AT = SPLIT_A ? 2 * AE : AE;
    constexpr int BE = TRANSB ? 128 * LDA : 32 * LDB_NN; // 5120 / 4352
    __half* sAh = sb;
    __half* sAl = sb + AE;
    __half* sBh = sb + AT;
    __half* sBl = sb + AT + BE;

#pragma unroll
    for (int i = 0; i < 2; i++) {
        int c = tid + (i << 8);
        int row = c >> 2, col = (c & 3) << 3;
        size_t g = (size_t)row * K + k0 + col;
        uint32_t so = row * LDA + col;
        cp16(cvta_s(sAh + so), Ah + g);
        if (SPLIT_A) cp16(cvta_s(sAl + so), Al + g);
    }
    if (TRANSB) {
#pragma unroll
        for (int i = 0; i < 2; i++) {
            int c = tid + (i << 8);
            int row = c >> 2, col = (c & 3) << 3;
            size_t g = (size_t)row * K + k0 + col;
            uint32_t so = row * LDA + col;
            cp16(cvta_s(sBh + so), Bh + g);
            if (SPLIT_B) cp16(cvta_s(sBl + so), Bl + g);
        }
    } else {
#pragma unroll
        for (int i = 0; i < 2; i++) {
            int c = tid + (i << 8);
            int row = c >> 4, col = (c & 15) << 3;
            size_t g = (size_t)(k0 + row) * N + col;
            uint32_t so = row * LDB_NN + col;
            cp16(cvta_s(sBh + so), Bh + g);
            if (SPLIT_B) cp16(cvta_s(sBl + so), Bl + g);
        }
    }
    asm volatile("cp.async.commit_group;");
}

template <bool TRANSB, bool SPLIT_A, bool SPLIT_B, int OUT>
__global__ __launch_bounds__(256, 2)
void gemm17(const __half* __restrict__ Agh, const __half* __restrict__ Agl,
            const __half* __restrict__ Bgh, const __half* __restrict__ Bgl,
            float* __restrict__ Cf,
            __half* __restrict__ Ch, __half* __restrict__ Cl,
            const float* __restrict__ b0, const float* __restrict__ b1,
            const float* __restrict__ b2,
            float* __restrict__ rsum,
            const __half* __restrict__ A2h, const __half* __restrict__ A2l,
            const __half* __restrict__ B2h, const __half* __restrict__ B2l,
            __half* __restrict__ C2h, __half* __restrict__ C2l,
            int N, int K, float alpha,
            size_t sA, size_t sB, size_t sC)
{
    extern __shared__ __align__(16) char smraw[];
    __half* sm = (__half*)smraw;
    constexpr int AE    = 128 * LDA;
    constexpr int AT    = SPLIT_A ? 2 * AE : AE;
    constexpr int BE    = TRANSB ? 128 * LDA : 32 * LDB_NN;
    constexpr int BT    = SPLIT_B ? 2 * BE : BE;
    constexpr int STAGE = AT + BT;
    constexpr int LDB   = TRANSB ? LDA : LDB_NN;

    const int tid  = threadIdx.x;
    const int lane = tid & 31;
    const int warp = tid >> 5;
    const int wm   = warp & 1;    // 2 row groups of 64
    const int wn   = warp >> 1;   // 4 col groups of 32
    const int z    = blockIdx.z;
    const int bm = blockIdx.y << 7, bn = blockIdx.x << 7;

    const float* bias = (z == 0) ? b0 : (z == 1) ? b1 : b2;

    const __half *Abh, *Abl = nullptr, *Bbh, *Bbl = nullptr;
    __half *Cho = nullptr, *Clo = nullptr;   // OUT==1 destinations

    if (OUT == 1 && z == 2) {
        // Wvo slice: A = Wv (hi/lo) [1024,K], B = Wo (hi/lo) [K,N] NN
        if (blockIdx.y >= 8) return;
        Abh = A2h + (size_t)bm * K;
        Abl = A2l + (size_t)bm * K;
        Bbh = B2h + bn;
        Bbl = B2l + bn;
        Cho = C2h;
        Clo = C2l;
    } else {
        Abh = Agh + z * sA + (size_t)bm * K;
        if (SPLIT_A) Abl = Agl + z * sA + (size_t)bm * K;
        if (TRANSB) {
            Bbh = Bgh + z * sB + (size_t)bn * K;
            if (SPLIT_B) Bbl = Bgl + z * sB + (size_t)bn * K;
        } else {
            Bbh = Bgh + z * sB + bn;
            if (SPLIT_B) Bbl = Bgl + z * sB + bn;
        }
        if (OUT == 1) { Cho = Ch + z * sC; Clo = Cl + z * sC; }
    }

    float acc[4][4][4];
#pragma unroll
    for (int i = 0; i < 4; i++)
#pragma unroll
        for (int j = 0; j < 4; j++)
#pragma unroll
            for (int l = 0; l < 4; l++) acc[i][j][l] = 0.f;

    const int lm_r = lane & 15;
    const int lm_c = (lane >> 4) << 3;
    const int tr_k = (lane & 7) | (((lane >> 3) & 1) << 3);
    const int tr_n = (lane >> 4) << 3;

    load_stage17<TRANSB, SPLIT_A, SPLIT_B>(sm, Abh, Abl, Bbh, Bbl, 0, K, N, tid);

    const int nT = K >> 5;
    for (int kt = 0; kt < nT; kt++) {
        asm volatile("cp.async.wait_group 0;");
        __syncthreads();
        if (kt + 1 < nT)
            load_stage17<TRANSB, SPLIT_A, SPLIT_B>(sm + ((kt + 1) & 1) * STAGE,
                                                   Abh, Abl, Bbh, Bbl,
                                                   (kt + 1) << 5, K, N, tid);

        __half* cs  = sm + (kt & 1) * STAGE;
        __half* sAh = cs;
        __half* sAl = cs + AE;
        __half* sBh = cs + AT;
        __half* sBl = cs + AT + BE;

#pragma unroll
        for (int ks = 0; ks < 2; ks++) {
            uint32_t af[4][4], bh[4][2], bl[4][2];

            if (TRANSB) {
#pragma unroll
                for (int h = 0; h < 2; h++) {
                    int row = wn * 32 + h * 16 + lm_r;
                    int col = ks * 16 + lm_c;
                    uint32_t t[4];
                    ldmx4(t, cvta_s(&sBh[row * LDB + col]));
                    bh[2 * h][0] = t[0]; bh[2 * h][1] = t[2];
                    bh[2 * h + 1][0] = t[1]; bh[2 * h + 1][1] = t[3];
                    if (SPLIT_B) {
                        ldmx4(t, cvta_s(&sBl[row * LDB + col]));
                        bl[2 * h][0] = t[0]; bl[2 * h][1] = t[2];
                        bl[2 * h + 1][0] = t[1]; bl[2 * h + 1][1] = t[3];
                    }
                }
            } else {
                int krow = ks * 16 + tr_k;
#pragma unroll
                for (int h = 0; h < 2; h++) {
                    int col = wn * 32 + h * 16 + tr_n;
                    uint32_t t[4];
                    ldmx4t(t, cvta_s(&sBh[krow * LDB + col]));
                    bh[2 * h][0] = t[0]; bh[2 * h][1] = t[1];
                    bh[2 * h + 1][0] = t[2]; bh[2 * h + 1][1] = t[3];
                    if (SPLIT_B) {
                        ldmx4t(t, cvta_s(&sBl[krow * LDB + col]));
                        bl[2 * h][0] = t[0]; bl[2 * h][1] = t[1];
                        bl[2 * h + 1][0] = t[2]; bl[2 * h + 1][1] = t[3];
                    }
                }
            }

            // pass 1 (+2): Ah*Bh (+ Ah*Bl)
#pragma unroll
            for (int mf = 0; mf < 4; mf++) {
                int row = wm * 64 + mf * 16 + lm_r;
                ldmx4(af[mf], cvta_s(&sAh[row * LDA + ks * 16 + lm_c]));
            }
#pragma unroll
            for (int mf = 0; mf < 4; mf++)
#pragma unroll
                for (int nf = 0; nf < 4; nf++) {
                    mma16816(acc[mf][nf], af[mf], bh[nf]);
                    if (SPLIT_B) mma16816(acc[mf][nf], af[mf], bl[nf]);
                }
            if (SPLIT_A) {
                // pass 3: Al*Bh
#pragma unroll
                for (int mf = 0; mf < 4; mf++) {
                    int row = wm * 64 + mf * 16 + lm_r;
                    ldmx4(af[mf], cvta_s(&sAl[row * LDA + ks * 16 + lm_c]));
                }
#pragma unroll
                for (int mf = 0; mf < 4; mf++)
#pragma unroll
                    for (int nf = 0; nf < 4; nf++)
                        mma16816(acc[mf][nf], af[mf], bh[nf]);
            }
        }
    }

    // ---- epilogue
    const int g  = lane >> 2;
    const int t2 = (lane & 3) << 1;

    if (OUT == 3) {
        // exp + un-normalized P (fp16) + atomic row sums
        __half* Chb = Ch + z * sC + (size_t)bm * N + bn;
        float rs[4][2];
#pragma unroll
        for (int mf = 0; mf < 4; mf++) { rs[mf][0] = 0.f; rs[mf][1] = 0.f; }
#pragma unroll
        for (int mf = 0; mf < 4; mf++) {
            int r0 = wm * 64 + mf * 16 + g;
#pragma unroll
            for (int nf = 0; nf < 4; nf++) {
                int c = wn * 32 + nf * 8 + t2;
                float e00 = fminf(__expf(acc[mf][nf][0] * alpha - EXPC), 60000.f);
                float e01 = fminf(__expf(acc[mf][nf][1] * alpha - EXPC), 60000.f);
                float e10 = fminf(__expf(acc[mf][nf][2] * alpha - EXPC), 60000.f);
                float e11 = fminf(__expf(acc[mf][nf][3] * alpha - EXPC), 60000.f);
                *(__half2*)(Chb + (size_t)r0 * N + c)       = hi2(e00, e01);
                *(__half2*)(Chb + (size_t)(r0 + 8) * N + c) = hi2(e10, e11);
                rs[mf][0] += e00 + e01;
                rs[mf][1] += e10 + e11;
            }
        }
#pragma unroll
        for (int mf = 0; mf < 4; mf++)
#pragma unroll
            for (int s = 0; s < 2; s++) {
                float v = rs[mf][s];
                v += __shfl_xor_sync(0xffffffffu, v, 1);
                v += __shfl_xor_sync(0xffffffffu, v, 2);
                rs[mf][s] = v;
            }
        float* rows = (float*)smraw;   // reuse stage smem (mainloop done)
        __syncthreads();
        if (tid < 128) rows[tid] = 0.f;
        __syncthreads();
        if ((lane & 3) == 0) {
#pragma unroll
            for (int mf = 0; mf < 4; mf++) {
                atomicAdd(&rows[wm * 64 + mf * 16 + g],     rs[mf][0]);
                atomicAdd(&rows[wm * 64 + mf * 16 + g + 8], rs[mf][1]);
            }
        }
        __syncthreads();
        if (tid < 128)
            atomicAdd(&rsum[(size_t)z * SEQ + bm + tid], rows[tid]);
        return;
    }

#pragma unroll
    for (int mf = 0; mf < 4; mf++) {
        int r0 = wm * 64 + mf * 16 + g;
        float sc0 = alpha, sc1 = alpha;
        if (OUT == 5) {
            sc0 = 1.f / rsum[(size_t)z * SEQ + bm + r0];
            sc1 = 1.f / rsum[(size_t)z * SEQ + bm + r0 + 8];
        }
#pragma unroll
        for (int nf = 0; nf < 4; nf++) {
            int c = wn * 32 + nf * 8 + t2;
            float bb0 = 0.f, bb1 = 0.f;
            if (bias) { bb0 = bias[bn + c]; bb1 = bias[bn + c + 1]; }
            float v00 = acc[mf][nf][0] * sc0 + bb0;
            float v01 = acc[mf][nf][1] * sc0 + bb1;
            float v10 = acc[mf][nf][2] * sc1 + bb0;
            float v11 = acc[mf][nf][3] * sc1 + bb1;
            if (OUT == 1) {
                __half* Chb = Cho + (size_t)bm * N + bn;
                __half* Clb = Clo + (size_t)bm * N + bn;
                __half2 h0 = hi2(v00, v01), h1 = hi2(v10, v11);
                __half2 L0 = lo2(v00, v01, h0), L1 = lo2(v10, v11, h1);
                *(__half2*)(Chb + (size_t)r0 * N + c)       = h0;
                *(__half2*)(Chb + (size_t)(r0 + 8) * N + c) = h1;
                *(__half2*)(Clb + (size_t)r0 * N + c)       = L0;
                *(__half2*)(Clb + (size_t)(r0 + 8) * N + c) = L1;
            } else if (OUT == 2) {
                __half* Chb = Ch + z * sC + (size_t)bm * N + bn;
                *(__half2*)(Chb + (size_t)r0 * N + c)       = hi2(v00, v01);
                *(__half2*)(Chb + (size_t)(r0 + 8) * N + c) = hi2(v10, v11);
            } else {
                float* Cfb = Cf + z * sC + (size_t)bm * N + bn;
                *(float2*)(Cfb + (size_t)r0 * N + c)       = make_float2(v00, v01);
                *(float2*)(Cfb + (size_t)(r0 + 8) * N + c) = make_float2(v10, v11);
            }
        }
    }
}

// ---------------------------------------------------------------------------
// merged elementwise split: x, Wq, Wk, Wv, Wo -> fp16 hi/lo; zeros R.
// ---------------------------------------------------------------------------
constexpr int NX4 = (int)(NQ / 4);   // 2097152
constexpr int NW4 = (int)(NW / 4);   // 262144

__global__ __launch_bounds__(256)
void split_all(const float* __restrict__ x,
               const float* __restrict__ Wq, const float* __restrict__ Wk,
               const float* __restrict__ Wv, const float* __restrict__ Wo,
               __half* __restrict__ xh, __half* __restrict__ xl,
               __half* __restrict__ W3h, __half* __restrict__ W3l,
               __half* __restrict__ Woh, __half* __restrict__ Wol,
               float* __restrict__ R)
{
    int i = blockIdx.x * blockDim.x + threadIdx.x;
    if (i < 2048) ((float4*)R)[i] = make_float4(0.f, 0.f, 0.f, 0.f);

    const float* src;
    __half *dh, *dl;
    int o;
    if (i < NX4) {
        src = x; dh = xh; dl = xl; o = i;
    } else {
        int j = i - NX4;
        int r = j >> 18;            // / NW4
        o = j & (NW4 - 1);
        if      (r == 0) { src = Wq; dh = W3h;          dl = W3l; }
        else if (r == 1) { src = Wk; dh = W3h + NW;     dl = W3l + NW; }
        else if (r == 2) { src = Wv; dh = W3h + 2 * NW; dl = W3l + 2 * NW; }
        else             { src = Wo; dh = Woh;          dl = Wol; }
    }
    float4 v = ((const float4*)src)[o];
    __half2 h0 = hi2(v.x, v.y), h1 = hi2(v.z, v.w);
    __half2 l0 = lo2(v.x, v.y, h0), l1 = lo2(v.z, v.w, h1);
    ((__half2*)dh)[2 * o]     = h0;
    ((__half2*)dh)[2 * o + 1] = h1;
    ((__half2*)dl)[2 * o]     = l0;
    ((__half2*)dl)[2 * o + 1] = l1;
}

// bcomb[j] = sum_d bv[d]*Wo[d][j] + bo[j].  Single-shot, side stream.
__global__ __launch_bounds__(256)
void bcomb_k(const float* __restrict__ bv, const float* __restrict__ Wo,
             const float* __restrict__ bo, float* __restrict__ bc)
{
    int j = blockIdx.x * 256 + threadIdx.x;
    float s = bo[j];
#pragma unroll 4
    for (int d = 0; d < DIM; d++)
        s += bv[d] * Wo[(size_t)d * DIM + j];
    bc[j] = s;
}

// ---------------------------------------------------------------------------
// kernel_launch — forked streams; per-batch scores -> PV pipeline.
// ---------------------------------------------------------------------------
extern "C" void kernel_launch(void* const* d_in, const int* in_sizes, int n_in,
                              void* d_out, int out_size)
{
    const float* x  = (const float*)d_in[0];
    const float* Wq = (const float*)d_in[1];
    const float* bq = (const float*)d_in[2];
    const float* Wk = (const float*)d_in[3];
    const float* bk = (const float*)d_in[4];
    const float* Wv = (const float*)d_in[5];
    const float* bv = (const float*)d_in[6];
    const float* Wo = (const float*)d_in[7];
    const float* bo = (const float*)d_in[8];
    float* out = (float*)d_out;

    __half *xh, *xl, *W3h, *W3l, *Woh, *Wol, *QKVh, *QKVl, *U, *P;
    float *R, *BC;
    cudaGetSymbolAddress((void**)&xh, g_xh);     cudaGetSymbolAddress((void**)&xl, g_xl);
    cudaGetSymbolAddress((void**)&W3h, g_W3h);   cudaGetSymbolAddress((void**)&W3l, g_W3l);
    cudaGetSymbolAddress((void**)&Woh, g_Woh);   cudaGetSymbolAddress((void**)&Wol, g_Wol);
    cudaGetSymbolAddress((void**)&QKVh, g_QKVh); cudaGetSymbolAddress((void**)&QKVl, g_QKVl);
    cudaGetSymbolAddress((void**)&U, g_O);       cudaGetSymbolAddress((void**)&P, g_P);
    cudaGetSymbolAddress((void**)&R, g_R);       cudaGetSymbolAddress((void**)&BC, g_BC);

    __half* Wvoh = QKVh + 2 * NQ;   // Wvo hi (old V slot)
    __half* Wvol = QKVl + 2 * NQ;   // Wvo lo scratch (unused downstream)

    // dynamic smem bytes (2 stages)
    const int SM_PROJ = 2 * 2 * (2 * 128 * LDA + 2 * 32 * LDB_NN);  // 75776
    const int SM_SC2  = 2 * 2 * (128 * LDA + 2 * 128 * LDA);        // 61440
    const int SM_1P   = 2 * 2 * (128 * LDA + 32 * LDB_NN);          // 37888
    cudaFuncSetAttribute(gemm17<false, true,  true,  1>, cudaFuncAttributeMaxDynamicSharedMemorySize, SM_PROJ);
    cudaFuncSetAttribute(gemm17<true,  false, true,  3>, cudaFuncAttributeMaxDynamicSharedMemorySize, SM_SC2);
    cudaFuncSetAttribute(gemm17<false, false, false, 2>, cudaFuncAttributeMaxDynamicSharedMemorySize, SM_1P);
    cudaFuncSetAttribute(gemm17<false, false, false, 5>, cudaFuncAttributeMaxDynamicSharedMemorySize, SM_1P);

    const int M = BATCH * SEQ;          // 8192
    const float scale = 0.125f;         // 1/sqrt(64)
    dim3 b256(256);
    const size_t sQ = (size_t)SEQ * DIM;
    const size_t sP = (size_t)SEQ * SEQ;

    // side stream + events
    cudaStream_t s2;
    cudaStreamCreate(&s2);
    cudaEvent_t ev0, evA, evU, evS0, evP0;
    cudaEventCreateWithFlags(&ev0,  cudaEventDisableTiming);
    cudaEventCreateWithFlags(&evA,  cudaEventDisableTiming);
    cudaEventCreateWithFlags(&evU,  cudaEventDisableTiming);
    cudaEventCreateWithFlags(&evS0, cudaEventDisableTiming);
    cudaEventCreateWithFlags(&evP0, cudaEventDisableTiming);

    // fork
    cudaEventRecord(ev0, 0);
    cudaStreamWaitEvent(s2, ev0, 0);

    // side: bcomb (raw inputs only) — hidden under split_all + QK
    bcomb_k<<<DIM / 256, b256, 0, s2>>>(bv, Wo, bo, BC);

    // main: merged pre-split + zero R
    split_all<<<(NX4 + 4 * NW4) / 256, b256>>>(x, Wq, Wk, Wv, Wo,
                                               xh, xl, W3h, W3l, Woh, Wol, R);

    // main: QK projection + Wvo (z in {0,1} -> Q,K; z==2 -> Wvo)
    dim3 gQK(DIM / 128, M / 128, 3);
    gemm17<false, true, true, 1><<<gQK, b256, SM_PROJ>>>(
        xh, xl, W3h, W3l, nullptr, QKVh, QKVl, bq, bk, nullptr, nullptr,
        W3h + 2 * NW, W3l + 2 * NW, Woh, Wol, Wvoh, Wvol,
        DIM, DIM, 1.f, 0, NW, NQ);
    cudaEventRecord(evA, 0);

    // side: U = x @ Wvo (1-pass) — overlaps scores(b0)
    cudaStreamWaitEvent(s2, evA, 0);
    dim3 gU(DIM / 128, M / 128, 1);
    gemm17<false, false, false, 2><<<gU, b256, SM_1P, s2>>>(
        xh, nullptr, Wvoh, nullptr, nullptr, U, nullptr,
        nullptr, nullptr, nullptr, nullptr,
        nullptr, nullptr, nullptr, nullptr, nullptr, nullptr,
        DIM, DIM, 1.f, 0, 0, 0);
    cudaEventRecord(evU, s2);

    __half *Qh = QKVh;
    __half *Kh = QKVh + NQ, *Kl = QKVl + NQ;

    // main: scores(b0) — batch-0 pointers, z = 0
    dim3 gSc1(SEQ / 128, SEQ / 128, 1);
    gemm17<true, false, true, 3><<<gSc1, b256, SM_SC2>>>(
        Qh, nullptr, Kh, Kl, nullptr, P, nullptr, nullptr, nullptr, nullptr, R,
        nullptr, nullptr, nullptr, nullptr, nullptr, nullptr,
        SEQ, DIM, scale, 0, 0, 0);
    cudaEventRecord(evS0, 0);

    // main: scores(b1)
    gemm17<true, false, true, 3><<<gSc1, b256, SM_SC2>>>(
        Qh + sQ, nullptr, Kh + sQ, Kl + sQ, nullptr, P + sP, nullptr,
        nullptr, nullptr, nullptr, R + SEQ,
        nullptr, nullptr, nullptr, nullptr, nullptr, nullptr,
        SEQ, DIM, scale, 0, 0, 0);

    // side: PV(b0) = (P0 @ U0)/R0 + BC — overlaps scores(b1).
    // Ordering on s2: bcomb -> U -> (wait evS0) -> PV(b0).
    cudaStreamWaitEvent(s2, evS0, 0);
    dim3 gPV1(DIM / 128, SEQ / 128, 1);
    gemm17<false, false, false, 5><<<gPV1, b256, SM_1P, s2>>>(
        P, nullptr, U, nullptr, out, nullptr, nullptr,
        BC, nullptr, nullptr, R,
        nullptr, nullptr, nullptr, nullptr, nullptr, nullptr,
        DIM, SEQ, 1.f, 0, 0, 0);
    cudaEventRecord(evP0, s2);

    // main: PV(b1) — needs U + BC (via evU, which follows bcomb on s2)
    cudaStreamWaitEvent(0, evU, 0);
    gemm17<false, false, false, 5><<<gPV1, b256, SM_1P>>>(
        P + sP, nullptr, U + sQ, nullptr, out + sQ, nullptr, nullptr,
        BC, nullptr, nullptr, R + SEQ,
        nullptr, nullptr, nullptr, nullptr, nullptr, nullptr,
        DIM, SEQ, 1.f, 0, 0, 0);

    // join: side PV(b0) must complete before the graph ends
    cudaStreamWaitEvent(0, evP0, 0);
}